// round 6
// baseline (speedup 1.0000x reference)
#include <cuda_runtime.h>
#include <math.h>

// ---------------- problem constants ----------------
#define B_  4
#define C_  192
#define T_  2048
#define H_  2
#define KC_ 96
#define FC_ 768
#define L_  6
#define SCALE_ 0.10206207261596577f   // 96^-0.5
#define EPS_ 1e-5f

// ---------------- packed f32x2 helpers (Blackwell FFMA2 path) ----------------
typedef unsigned long long ull;
__device__ __forceinline__ ull ffma2(ull a, ull b, ull c) {
    ull d; asm("fma.rn.f32x2 %0, %1, %2, %3;" : "=l"(d) : "l"(a), "l"(b), "l"(c));
    return d;
}
__device__ __forceinline__ ull fmul2(ull a, ull b) {
    ull d; asm("mul.rn.f32x2 %0, %1, %2;" : "=l"(d) : "l"(a), "l"(b));
    return d;
}
__device__ __forceinline__ ull fdup(float x) {
    ull r; asm("mov.b64 %0, {%1, %2};" : "=l"(r) : "f"(x), "f"(x));
    return r;
}
__device__ __forceinline__ ull fpack(float lo, float hi) {
    ull r; asm("mov.b64 %0, {%1, %2};" : "=l"(r) : "f"(lo), "f"(hi));
    return r;
}
__device__ __forceinline__ float2 funpack(ull v) {
    float2 f; asm("mov.b64 {%0, %1}, %2;" : "=f"(f.x), "=f"(f.y) : "l"(v));
    return f;
}

// ---------------- scratch (no allocations allowed) ----------------
__device__ float g_x[B_*C_*T_];
__device__ float g_q[B_*C_*T_];
__device__ float g_k[B_*C_*T_];
__device__ float g_v[B_*C_*T_];
__device__ float g_a[B_*C_*T_];   // attention O, half 0 -> combined
__device__ float g_a2[B_*C_*T_];  // attention O, half 1
__device__ float g_t[B_*C_*T_];
__device__ float g_f[B_*FC_*T_];
__device__ float g_m[B_*H_*T_],  g_l[B_*H_*T_];    // half 0 stats
__device__ float g_m2[B_*H_*T_], g_l2[B_*H_*T_];   // half 1 stats

// ---------------- elementwise mask multiply ----------------
__global__ void k_maskmul(const float* __restrict__ in, const float* __restrict__ msk,
                          float* __restrict__ out)
{
    int idx = blockIdx.x * blockDim.x + threadIdx.x;
    if (idx >= B_*C_*T_) return;
    int b = idx / (C_*T_);
    int t = idx % T_;
    out[idx] = in[idx] * msk[b*T_ + t];
}

// ---------------- shared GEMM/conv microkernel body ----------------
// Y[o, t0..t0+BN) = bias[o] + sum_{c,k} W[o,c,k] * X[c, t+k-pad], optional relu.
// 128 threads. BM=64 rows. BN in {32,64}. Per-thread RPT rows x 4 cols (FFMA2 pairs).
template<int KW, int BN>
__device__ __forceinline__ void gemm_body(
    const float* __restrict__ Xb, const float* __restrict__ Wg,
    const float* __restrict__ bias, float* __restrict__ Yb,
    int M, int Cin, int relu, int m0, int t0)
{
    constexpr int BM = 64, BK = 16;
    constexpr int PADW = (KW - 1) / 2;
    constexpr int XV = BN + KW - 1;      // valid halo width
    constexpr int XW = BN + 4;           // padded X row stride
    constexpr int TX = BN / 4;           // lanes over cols
    constexpr int TY = 128 / TX;         // groups over rows
    constexpr int RPT = BM / TY;         // rows per thread (4 or 8)

    __shared__ float Ws[KW][BK][68];     // [k][c][o], padded o-stride
    __shared__ float Xs[BK][XW];

    const int tid = threadIdx.x;
    const int tx = tid % TX, ty = tid / TX;

    ull acc[RPT][2] = {};

    for (int c0 = 0; c0 < Cin; c0 += BK) {
        for (int idx = tid; idx < BM*BK*KW; idx += 128) {
            int o  = idx / (BK*KW);
            int ck = idx - o * (BK*KW);
            int c  = ck / KW, k = ck - c * KW;
            Ws[k][c][o] = Wg[((size_t)(m0 + o) * Cin + c0 + c) * KW + k];
        }
        for (int idx = tid; idx < BK*XV; idx += 128) {
            int c = idx / XV, u = idx - c * XV;
            int t = t0 - PADW + u;
            Xs[c][u] = (t >= 0 && t < T_) ? Xb[(size_t)(c0 + c) * T_ + t] : 0.f;
        }
        __syncthreads();

        #pragma unroll
        for (int cc = 0; cc < BK; cc++) {
            float4 xb0 = *(const float4*)&Xs[cc][tx*4];
            float xb4 = 0.f, xb5 = 0.f;
            if (KW == 3) { xb4 = Xs[cc][tx*4 + 4]; xb5 = Xs[cc][tx*4 + 5]; }

            #pragma unroll
            for (int k = 0; k < KW; k++) {
                ull bp0, bp1;
                if (k == 0)      { bp0 = fpack(xb0.x, xb0.y); bp1 = fpack(xb0.z, xb0.w); }
                else if (k == 1) { bp0 = fpack(xb0.y, xb0.z); bp1 = fpack(xb0.w, xb4);   }
                else             { bp0 = fpack(xb0.z, xb0.w); bp1 = fpack(xb4,   xb5);   }

                float av[RPT];
                #pragma unroll
                for (int q = 0; q < RPT/4; q++) {
                    float4 a4 = *(const float4*)&Ws[k][cc][ty*RPT + q*4];
                    av[q*4+0] = a4.x; av[q*4+1] = a4.y; av[q*4+2] = a4.z; av[q*4+3] = a4.w;
                }
                #pragma unroll
                for (int i = 0; i < RPT; i++) {
                    ull ad = fdup(av[i]);
                    acc[i][0] = ffma2(ad, bp0, acc[i][0]);
                    acc[i][1] = ffma2(ad, bp1, acc[i][1]);
                }
            }
        }
        __syncthreads();
    }

    #pragma unroll
    for (int i = 0; i < RPT; i++) {
        int o = m0 + ty*RPT + i;
        float bb = bias[o];
        float2 lo = funpack(acc[i][0]);
        float2 hi = funpack(acc[i][1]);
        float4 r = make_float4(lo.x + bb, lo.y + bb, hi.x + bb, hi.y + bb);
        if (relu) {
            r.x = fmaxf(r.x, 0.f); r.y = fmaxf(r.y, 0.f);
            r.z = fmaxf(r.z, 0.f); r.w = fmaxf(r.w, 0.f);
        }
        *reinterpret_cast<float4*>(&Yb[(size_t)o * T_ + t0 + tx*4]) = r;
    }
}

template<int KW, int BN>
__global__ __launch_bounds__(128) void k_gemm(
    const float* __restrict__ X, const float* __restrict__ Wg,
    const float* __restrict__ bias, float* __restrict__ Y,
    int M, int Cin, int relu)
{
    const int b = blockIdx.z;
    gemm_body<KW, BN>(X + (size_t)b * Cin * T_, Wg, bias, Y + (size_t)b * M * T_,
                      M, Cin, relu, blockIdx.y * 64, blockIdx.x * BN);
}

// fused Q/K/V projection: grid.y = 9 -> (matrix, m-tile)
__global__ __launch_bounds__(128) void k_qkv(
    const float* __restrict__ X,
    const float* __restrict__ Wq, const float* __restrict__ bq, float* __restrict__ Yq,
    const float* __restrict__ Wk, const float* __restrict__ bk, float* __restrict__ Yk,
    const float* __restrict__ Wv, const float* __restrict__ bv, float* __restrict__ Yv)
{
    const int b = blockIdx.z;
    const int mat = blockIdx.y / 3;
    const int m0  = (blockIdx.y % 3) * 64;
    const float *W, *bi; float *Y;
    if (mat == 0)      { W = Wq; bi = bq; Y = Yq; }
    else if (mat == 1) { W = Wk; bi = bk; Y = Yk; }
    else               { W = Wv; bi = bv; Y = Yv; }
    gemm_body<1, 64>(X + (size_t)b * C_ * T_, W, bi, Y + (size_t)b * C_ * T_,
                     C_, C_, 0, m0, blockIdx.x * 64);
}

// ---------------- flash attention, 2-way split-KV, relative-K band ----------------
// grid.y = half*H + h; each block covers s in [half*T/2, (half+1)*T/2)
__global__ __launch_bounds__(256) void k_flash(
    const float* __restrict__ Q, const float* __restrict__ Kp, const float* __restrict__ V,
    const float* __restrict__ erk,
    float* __restrict__ O1, float* __restrict__ O2,
    float* __restrict__ M1, float* __restrict__ L1,
    float* __restrict__ M2, float* __restrict__ L2)
{
    constexpr int BR = 64, BC = 64, D = 96, VSTR = 98;
    extern __shared__ float sm[];
    float* Qs = sm;                 // D*BR     [d][r]
    float* Ks = Qs + D*BR;          // D*BC     [d][c]
    float* Vs = Ks + D*BC;          // BC*VSTR  [s][d]
    float* Ps = Vs + BC*VSTR;       // BR*BC
    float* qr = Ps + BR*BC;         // BR*9

    const int t0 = blockIdx.x * BR;
    const int h = blockIdx.y % H_, half = blockIdx.y / H_;
    const int b = blockIdx.z;
    const int sbeg = half * (T_/2), send = sbeg + T_/2;
    float* O  = half ? O2 : O1;
    float* Mo = half ? M2 : M1;
    float* Lo = half ? L2 : L1;

    const size_t base = ((size_t)b * C_ + h * KC_) * T_;
    const float* Qb = Q + base;
    const float* Kb = Kp + base;
    const float* Vb = V + base;

    const int tid = threadIdx.x;
    const int tx = tid & 15, ty = tid >> 4;

    for (int idx = tid; idx < D*BR; idx += 256) {
        int d = idx / BR, r = idx - d * BR;
        Qs[idx] = Qb[(size_t)d * T_ + t0 + r] * SCALE_;
    }
    __syncthreads();
    for (int idx = tid; idx < BR * 9; idx += 256) {
        int r = idx / 9, dd = idx - r * 9;
        float s = 0.f;
        #pragma unroll 8
        for (int d = 0; d < D; d++) s = fmaf(Qs[d*BR + r], erk[dd*KC_ + d], s);
        qr[idx] = s;
    }

    float m_i[4], l_i[4];
    ull oa[4][3];
    #pragma unroll
    for (int i = 0; i < 4; i++) {
        m_i[i] = -1e30f; l_i[i] = 0.f;
        #pragma unroll
        for (int j = 0; j < 3; j++) oa[i][j] = 0ull;
    }

    for (int s0 = sbeg; s0 < send; s0 += BC) {
        __syncthreads();
        for (int idx = tid; idx < D*BC; idx += 256) {
            int d = idx / BC, c = idx - d * BC;
            Ks[d*BC + c] = Kb[(size_t)d * T_ + s0 + c];
            Vs[c*VSTR + d] = Vb[(size_t)d * T_ + s0 + c];
        }
        __syncthreads();

        ull sc2[4][2] = {};
        #pragma unroll 4
        for (int d = 0; d < D; d++) {
            float4 a4 = *(const float4*)&Qs[d*BR + ty*4];
            float4 b4 = *(const float4*)&Ks[d*BC + tx*4];
            ull bp0 = fpack(b4.x, b4.y), bp1 = fpack(b4.z, b4.w);
            float av[4] = {a4.x, a4.y, a4.z, a4.w};
            #pragma unroll
            for (int i = 0; i < 4; i++) {
                ull ad = fdup(av[i]);
                sc2[i][0] = ffma2(ad, bp0, sc2[i][0]);
                sc2[i][1] = ffma2(ad, bp1, sc2[i][1]);
            }
        }
        float sc[4][4];
        #pragma unroll
        for (int i = 0; i < 4; i++) {
            float2 lo = funpack(sc2[i][0]), hi = funpack(sc2[i][1]);
            sc[i][0] = lo.x; sc[i][1] = lo.y; sc[i][2] = hi.x; sc[i][3] = hi.y;
        }

        if (s0 + BC + 4 > t0 && s0 < t0 + BR + 5) {
            #pragma unroll
            for (int i = 0; i < 4; i++)
                #pragma unroll
                for (int j = 0; j < 4; j++) {
                    int delta = (s0 + tx*4 + j) - (t0 + ty*4 + i);
                    if (delta >= -4 && delta <= 4)
                        sc[i][j] += qr[(ty*4 + i)*9 + delta + 4];
                }
        }

        #pragma unroll
        for (int i = 0; i < 4; i++) {
            float mx = fmaxf(fmaxf(sc[i][0], sc[i][1]), fmaxf(sc[i][2], sc[i][3]));
            #pragma unroll
            for (int off = 8; off; off >>= 1)
                mx = fmaxf(mx, __shfl_xor_sync(0xffffffffu, mx, off));
            float mn = fmaxf(m_i[i], mx);
            float al = __expf(m_i[i] - mn);
            float p0 = __expf(sc[i][0] - mn), p1 = __expf(sc[i][1] - mn);
            float p2 = __expf(sc[i][2] - mn), p3 = __expf(sc[i][3] - mn);
            *(float4*)&Ps[(ty*4 + i)*BC + tx*4] = make_float4(p0, p1, p2, p3);
            float rs = p0 + p1 + p2 + p3;
            #pragma unroll
            for (int off = 8; off; off >>= 1)
                rs += __shfl_xor_sync(0xffffffffu, rs, off);
            l_i[i] = l_i[i] * al + rs;
            m_i[i] = mn;
            ull al2 = fdup(al);
            #pragma unroll
            for (int j = 0; j < 3; j++) oa[i][j] = fmul2(oa[i][j], al2);
        }
        __syncthreads();

        #pragma unroll 2
        for (int s = 0; s < BC; s++) {
            ull pd[4];
            #pragma unroll
            for (int i = 0; i < 4; i++) pd[i] = fdup(Ps[(ty*4 + i)*BC + s]);
            const float* vrow = &Vs[s*VSTR + tx*6];
            ull v0 = *(const ull*)(vrow);
            ull v1 = *(const ull*)(vrow + 2);
            ull v2 = *(const ull*)(vrow + 4);
            #pragma unroll
            for (int i = 0; i < 4; i++) {
                oa[i][0] = ffma2(pd[i], v0, oa[i][0]);
                oa[i][1] = ffma2(pd[i], v1, oa[i][1]);
                oa[i][2] = ffma2(pd[i], v2, oa[i][2]);
            }
        }
    }
    __syncthreads();

    #pragma unroll
    for (int i = 0; i < 4; i++) {
        float inv = 1.f / l_i[i];
        #pragma unroll
        for (int j = 0; j < 3; j++) {
            float2 p = funpack(oa[i][j]);
            Qs[(tx*6 + j*2    )*BR + ty*4 + i] = p.x * inv;
            Qs[(tx*6 + j*2 + 1)*BR + ty*4 + i] = p.y * inv;
        }
    }
    if (tx == 0) {
        #pragma unroll
        for (int i = 0; i < 4; i++) {
            int t = t0 + ty*4 + i;
            Mo[((size_t)b*H_ + h)*T_ + t] = m_i[i];
            Lo[((size_t)b*H_ + h)*T_ + t] = l_i[i];
        }
    }
    __syncthreads();
    float* Ob = O + base;
    for (int idx = tid; idx < D*BR; idx += 256) {
        int d = idx / BR, r = idx - d * BR;
        Ob[(size_t)d * T_ + t0 + r] = Qs[idx];
    }
}

// ---------------- split-KV combine + relative-V band correction ----------------
// O = (w1*O1 + w2*O2)/(w1+w2) + sum_{delta} p[t,t+delta] * erv[delta+4, :]
__global__ __launch_bounds__(256) void k_relv(
    const float* __restrict__ Q, const float* __restrict__ Kp,
    const float* __restrict__ erk, const float* __restrict__ erv,
    const float* __restrict__ M1, const float* __restrict__ L1,
    const float* __restrict__ M2, const float* __restrict__ L2,
    float* __restrict__ O1, const float* __restrict__ O2)
{
    __shared__ float Qt[96*32];
    __shared__ float Kt[96*40];
    __shared__ float ek[9*96], ev[9*96];

    const int t0 = blockIdx.x * 32;
    const int h = blockIdx.y, b = blockIdx.z;
    const size_t base = ((size_t)b * C_ + h * KC_) * T_;
    const int tid = threadIdx.x;

    for (int idx = tid; idx < 96*32; idx += 256) {
        int d = idx / 32, u = idx - d * 32;
        Qt[idx] = Q[base + (size_t)d * T_ + t0 + u] * SCALE_;
    }
    for (int idx = tid; idx < 96*40; idx += 256) {
        int d = idx / 40, u = idx - d * 40;
        int t = t0 - 4 + u;
        Kt[idx] = (t >= 0 && t < T_) ? Kp[base + (size_t)d * T_ + t] : 0.f;
    }
    for (int idx = tid; idx < 9*96; idx += 256) { ek[idx] = erk[idx]; ev[idx] = erv[idx]; }
    __syncthreads();

    const int tx = tid & 31, g = tid >> 5;     // 32 t-lanes x 8 d-groups
    const int t = t0 + tx;
    const size_t bht = ((size_t)b*H_ + h)*T_ + t;
    const float m1 = M1[bht], l1v = L1[bht];
    const float m2 = M2[bht], l2v = L2[bht];
    const float mm = fmaxf(m1, m2);
    const float w1 = __expf(m1 - mm) * l1v;
    const float w2 = __expf(m2 - mm) * l2v;
    const float invl = 1.f / (w1 + w2);
    const float c1 = w1 * invl, c2 = w2 * invl;

    float p[9];
    #pragma unroll
    for (int dd = 0; dd < 9; dd++) {
        int s = t + dd - 4;
        if (s < 0 || s >= T_) { p[dd] = 0.f; continue; }
        float sc = 0.f;
        #pragma unroll 8
        for (int d = 0; d < 96; d++)
            sc = fmaf(Qt[d*32 + tx], Kt[d*40 + tx + dd] + ek[dd*96 + d], sc);
        p[dd] = __expf(sc - mm) * invl;
    }
    #pragma unroll
    for (int jd = 0; jd < 12; jd++) {
        int d = g * 12 + jd;
        size_t idx = base + (size_t)d * T_ + t;
        float add = 0.f;
        #pragma unroll
        for (int dd = 0; dd < 9; dd++) add = fmaf(p[dd], ev[dd*96 + d], add);
        O1[idx] = c1 * O1[idx] + c2 * O2[idx] + add;
    }
}

// ---------------- fused residual-add + channel LayerNorm ----------------
__global__ __launch_bounds__(256) void k_addln(
    float* __restrict__ X, const float* __restrict__ R,
    const float* __restrict__ gg, const float* __restrict__ be)
{
    const int tx = threadIdx.x, ty = threadIdx.y;
    const int t = blockIdx.x * 32 + tx;
    const int b = blockIdx.y;

    float vals[24];
    float s = 0.f, sq = 0.f;
    #pragma unroll
    for (int k = 0; k < 24; k++) {
        int c = ty + k * 8;
        size_t idx = ((size_t)b * C_ + c) * T_ + t;
        float v = X[idx] + R[idx];
        vals[k] = v; s += v; sq += v * v;
    }
    __shared__ float ss[8][33], sg[8][33];
    ss[ty][tx] = s; sg[ty][tx] = sq;
    __syncthreads();
    if (ty == 0) {
        float a = 0.f, q = 0.f;
        #pragma unroll
        for (int k = 0; k < 8; k++) { a += ss[k][tx]; q += sg[k][tx]; }
        ss[0][tx] = a; sg[0][tx] = q;
    }
    __syncthreads();
    const float mean = ss[0][tx] * (1.f / C_);
    const float var  = sg[0][tx] * (1.f / C_) - mean * mean;
    const float rstd = rsqrtf(var + EPS_);
    #pragma unroll
    for (int k = 0; k < 24; k++) {
        int c = ty + k * 8;
        size_t idx = ((size_t)b * C_ + c) * T_ + t;
        X[idx] = (vals[k] - mean) * rstd * gg[c] + be[c];
    }
}

// ---------------- launcher ----------------
extern "C" void kernel_launch(void* const* d_in, const int* in_sizes, int n_in,
                              void* d_out, int out_size)
{
    (void)in_sizes; (void)n_in; (void)out_size;
    const float* x   = (const float*)d_in[0];
    const float* msk = (const float*)d_in[1];
    const float* Wq  = (const float*)d_in[2];
    const float* bq  = (const float*)d_in[3];
    const float* Wk  = (const float*)d_in[4];
    const float* bk  = (const float*)d_in[5];
    const float* Wv  = (const float*)d_in[6];
    const float* bv  = (const float*)d_in[7];
    const float* Wo  = (const float*)d_in[8];
    const float* bo  = (const float*)d_in[9];
    const float* erk = (const float*)d_in[10];
    const float* erv = (const float*)d_in[11];
    const float* g1  = (const float*)d_in[12];
    const float* be1 = (const float*)d_in[13];
    const float* fw1 = (const float*)d_in[14];
    const float* fb1 = (const float*)d_in[15];
    const float* fw2 = (const float*)d_in[16];
    const float* fb2 = (const float*)d_in[17];
    const float* g2  = (const float*)d_in[18];
    const float* be2 = (const float*)d_in[19];

    float *xb, *qb, *kb, *vb, *ab, *a2, *tb, *fb, *mb, *lb, *m2, *l2;
    cudaGetSymbolAddress((void**)&xb, g_x);
    cudaGetSymbolAddress((void**)&qb, g_q);
    cudaGetSymbolAddress((void**)&kb, g_k);
    cudaGetSymbolAddress((void**)&vb, g_v);
    cudaGetSymbolAddress((void**)&ab, g_a);
    cudaGetSymbolAddress((void**)&a2, g_a2);
    cudaGetSymbolAddress((void**)&tb, g_t);
    cudaGetSymbolAddress((void**)&fb, g_f);
    cudaGetSymbolAddress((void**)&mb, g_m);
    cudaGetSymbolAddress((void**)&lb, g_l);
    cudaGetSymbolAddress((void**)&m2, g_m2);
    cudaGetSymbolAddress((void**)&l2, g_l2);

    constexpr int FLASH_SMEM = (96*64 + 96*64 + 64*98 + 64*64 + 64*9) * 4;
    cudaFuncSetAttribute(k_flash, cudaFuncAttributeMaxDynamicSharedMemorySize, FLASH_SMEM);

    k_maskmul<<<(B_*C_*T_ + 255)/256, 256>>>(x, msk, xb);

    for (int i = 0; i < L_; i++) {
        k_qkv<<<dim3(T_/64, 9, B_), 128>>>(
            xb,
            Wq + (size_t)i*C_*C_, bq + i*C_, qb,
            Wk + (size_t)i*C_*C_, bk + i*C_, kb,
            Wv + (size_t)i*C_*C_, bv + i*C_, vb);

        k_flash<<<dim3(T_/64, H_*2, B_), 256, FLASH_SMEM>>>(
            qb, kb, vb, erk + (size_t)i*9*KC_, ab, a2, mb, lb, m2, l2);
        k_relv<<<dim3(T_/32, H_, B_), 256>>>(
            qb, kb, erk + (size_t)i*9*KC_, erv + (size_t)i*9*KC_,
            mb, lb, m2, l2, ab, a2);

        k_gemm<1,32><<<dim3(T_/32, C_/64, B_), 128>>>(
            ab, Wo + (size_t)i*C_*C_, bo + i*C_, tb, C_, C_, 0);
        k_addln<<<dim3(T_/32, B_), dim3(32, 8)>>>(xb, tb, g1 + i*C_, be1 + i*C_);

        k_gemm<3,64><<<dim3(T_/64, FC_/64, B_), 128>>>(
            xb, fw1 + (size_t)i*FC_*C_*3, fb1 + i*FC_, fb, FC_, C_, 1);
        k_gemm<3,32><<<dim3(T_/32, C_/64, B_), 128>>>(
            fb, fw2 + (size_t)i*C_*FC_*3, fb2 + i*C_, tb, C_, FC_, 0);
        k_addln<<<dim3(T_/32, B_), dim3(32, 8)>>>(xb, tb, g2 + i*C_, be2 + i*C_);
    }

    k_maskmul<<<(B_*C_*T_ + 255)/256, 256>>>(xb, msk, (float*)d_out);
}

// round 7
// speedup vs baseline: 1.8237x; 1.8237x over previous
#include <cuda_runtime.h>
#include <math.h>

// ---------------- problem constants ----------------
#define B_  4
#define C_  192
#define T_  2048
#define H_  2
#define KC_ 96
#define FC_ 768
#define L_  6
#define SCALE_ 0.10206207261596577f   // 96^-0.5
#define EPS_ 1e-5f

// ---------------- packed f32x2 helpers (Blackwell FFMA2 path) ----------------
typedef unsigned long long ull;
__device__ __forceinline__ ull ffma2(ull a, ull b, ull c) {
    ull d; asm("fma.rn.f32x2 %0, %1, %2, %3;" : "=l"(d) : "l"(a), "l"(b), "l"(c));
    return d;
}
__device__ __forceinline__ ull fmul2(ull a, ull b) {
    ull d; asm("mul.rn.f32x2 %0, %1, %2;" : "=l"(d) : "l"(a), "l"(b));
    return d;
}
__device__ __forceinline__ ull fdup(float x) {
    ull r; asm("mov.b64 %0, {%1, %2};" : "=l"(r) : "f"(x), "f"(x));
    return r;
}
__device__ __forceinline__ ull fpack(float lo, float hi) {
    ull r; asm("mov.b64 %0, {%1, %2};" : "=l"(r) : "f"(lo), "f"(hi));
    return r;
}
__device__ __forceinline__ float2 funpack(ull v) {
    float2 f; asm("mov.b64 {%0, %1}, %2;" : "=f"(f.x), "=f"(f.y) : "l"(v));
    return f;
}

// ---------------- scratch (no allocations allowed) ----------------
__device__ float g_x[B_*C_*T_];
__device__ float g_q[B_*C_*T_];
__device__ float g_k[B_*C_*T_];
__device__ float g_v[B_*C_*T_];
__device__ float g_a[B_*C_*T_];
__device__ float g_t[B_*C_*T_];
__device__ float g_f[B_*FC_*T_];
__device__ float g_m[B_*H_*T_];
__device__ float g_l[B_*H_*T_];

// ---------------- elementwise mask multiply ----------------
__global__ void k_maskmul(const float* __restrict__ in, const float* __restrict__ msk,
                          float* __restrict__ out)
{
    int idx = blockIdx.x * blockDim.x + threadIdx.x;
    if (idx >= B_*C_*T_) return;
    int b = idx / (C_*T_);
    int t = idx % T_;
    out[idx] = in[idx] * msk[b*T_ + t];
}

// ---------------- GEMM/conv microkernel body (BN=64, FFMA2) ----------------
// Y[o, t0..t0+64) = bias?[o] + sum_{c in [c_begin,c_end), k} W[o,c,k] * X[c, t+k-pad]
// 128 threads, BM=BN=64, per-thread 8 rows x 4 cols (2 packed pairs).
template<int KW>
__device__ __forceinline__ void gemm_body(
    const float* __restrict__ Xb, const float* __restrict__ Wg,
    const float* __restrict__ bias, float* __restrict__ Yb,
    int Cin, int relu, int m0, int t0, int c_begin, int c_end)
{
    constexpr int BM = 64, BN = 64, BK = 16;
    constexpr int PADW = (KW - 1) / 2;
    constexpr int XV = BN + KW - 1;      // valid halo width
    constexpr int XW = 68;               // padded row stride (float4-safe)

    __shared__ float Ws[KW][BK][XW];     // [k][c][o] with padded o-stride
    __shared__ float Xs[BK][XW];

    const int tid = threadIdx.x;
    const int tx = tid & 15, ty = tid >> 4;   // tx: 16 x 4 cols, ty: 8 x 8 rows

    ull acc[8][2] = {};

    for (int c0 = c_begin; c0 < c_end; c0 += BK) {
        for (int idx = tid; idx < BM*BK*KW; idx += 128) {
            int o  = idx / (BK*KW);
            int ck = idx - o * (BK*KW);
            int c  = ck / KW, k = ck - c * KW;
            Ws[k][c][o] = Wg[((size_t)(m0 + o) * Cin + c0 + c) * KW + k];
        }
        for (int idx = tid; idx < BK*XV; idx += 128) {
            int c = idx / XV, u = idx - c * XV;
            int t = t0 - PADW + u;
            Xs[c][u] = (t >= 0 && t < T_) ? Xb[(size_t)(c0 + c) * T_ + t] : 0.f;
        }
        __syncthreads();

        #pragma unroll
        for (int cc = 0; cc < BK; cc++) {
            float4 xb0 = *(const float4*)&Xs[cc][tx*4];
            float xb4 = 0.f, xb5 = 0.f;
            if (KW == 3) { xb4 = Xs[cc][tx*4 + 4]; xb5 = Xs[cc][tx*4 + 5]; }

            #pragma unroll
            for (int k = 0; k < KW; k++) {
                ull bp0, bp1;
                if (k == 0)      { bp0 = fpack(xb0.x, xb0.y); bp1 = fpack(xb0.z, xb0.w); }
                else if (k == 1) { bp0 = fpack(xb0.y, xb0.z); bp1 = fpack(xb0.w, xb4);   }
                else             { bp0 = fpack(xb0.z, xb0.w); bp1 = fpack(xb4,   xb5);   }

                float4 a0 = *(const float4*)&Ws[k][cc][ty*8];
                float4 a1 = *(const float4*)&Ws[k][cc][ty*8 + 4];
                float av[8] = {a0.x, a0.y, a0.z, a0.w, a1.x, a1.y, a1.z, a1.w};
                #pragma unroll
                for (int i = 0; i < 8; i++) {
                    ull ad = fdup(av[i]);
                    acc[i][0] = ffma2(ad, bp0, acc[i][0]);
                    acc[i][1] = ffma2(ad, bp1, acc[i][1]);
                }
            }
        }
        __syncthreads();
    }

    #pragma unroll
    for (int i = 0; i < 8; i++) {
        int o = m0 + ty*8 + i;
        float bb = bias ? bias[o] : 0.f;
        float2 lo = funpack(acc[i][0]);
        float2 hi = funpack(acc[i][1]);
        float4 r = make_float4(lo.x + bb, lo.y + bb, hi.x + bb, hi.y + bb);
        if (relu) {
            r.x = fmaxf(r.x, 0.f); r.y = fmaxf(r.y, 0.f);
            r.z = fmaxf(r.z, 0.f); r.w = fmaxf(r.w, 0.f);
        }
        *reinterpret_cast<float4*>(&Yb[(size_t)o * T_ + t0 + tx*4]) = r;
    }
}

template<int KW>
__global__ __launch_bounds__(128) void k_gemm(
    const float* __restrict__ X, const float* __restrict__ Wg,
    const float* __restrict__ bias, float* __restrict__ Y,
    int M, int Cin, int relu)
{
    const int b = blockIdx.z;
    gemm_body<KW>(X + (size_t)b * Cin * T_, Wg, bias, Y + (size_t)b * M * T_,
                  Cin, relu, blockIdx.y * 64, blockIdx.x * 64, 0, Cin);
}

// fused Q/K/V projection: grid.y = 9 -> (matrix, m-tile), same BN=64 body
__global__ __launch_bounds__(128) void k_qkv(
    const float* __restrict__ X,
    const float* __restrict__ Wq, const float* __restrict__ bq, float* __restrict__ Yq,
    const float* __restrict__ Wk, const float* __restrict__ bk, float* __restrict__ Yk,
    const float* __restrict__ Wv, const float* __restrict__ bv, float* __restrict__ Yv)
{
    const int b = blockIdx.z;
    const int mat = blockIdx.y / 3;
    const int m0  = (blockIdx.y % 3) * 64;
    const float *W, *bi; float *Y;
    if (mat == 0)      { W = Wq; bi = bq; Y = Yq; }
    else if (mat == 1) { W = Wk; bi = bk; Y = Yk; }
    else               { W = Wv; bi = bv; Y = Yv; }
    gemm_body<1>(X + (size_t)b * C_ * T_, W, bi, Y + (size_t)b * C_ * T_,
                 C_, 0, m0, blockIdx.x * 64, 0, C_);
}

// split-K conv2: grid.y = 6 -> (half, m-tile). half 0 covers Cin [0,384) + bias,
// half 1 covers [384,768), no bias. Partials summed in k_addln3.
__global__ __launch_bounds__(128) void k_conv2split(
    const float* __restrict__ X, const float* __restrict__ Wg,
    const float* __restrict__ bias, float* __restrict__ Y1, float* __restrict__ Y2)
{
    const int b = blockIdx.z;
    const int half = blockIdx.y / 3;
    const int m0   = (blockIdx.y % 3) * 64;
    float* Y = half ? Y2 : Y1;
    gemm_body<3>(X + (size_t)b * FC_ * T_, Wg, half ? nullptr : bias,
                 Y + (size_t)b * C_ * T_, FC_, 0, m0, blockIdx.x * 64,
                 half * (FC_/2), (half + 1) * (FC_/2));
}

// ---------------- flash attention with relative-K band (FFMA2) ----------------
__global__ __launch_bounds__(256) void k_flash(
    const float* __restrict__ Q, const float* __restrict__ Kp, const float* __restrict__ V,
    const float* __restrict__ erk, float* __restrict__ O,
    float* __restrict__ Mo, float* __restrict__ Lo)
{
    constexpr int BR = 64, BC = 64, D = 96, VSTR = 98; // V stored [s][d], padded stride
    extern __shared__ float sm[];
    float* Qs = sm;                 // D*BR     [d][r]
    float* Ks = Qs + D*BR;          // D*BC     [d][c]
    float* Vs = Ks + D*BC;          // BC*VSTR  [s][d]
    float* Ps = Vs + BC*VSTR;       // BR*BC
    float* qr = Ps + BR*BC;         // BR*9

    const int t0 = blockIdx.x * BR;
    const int h = blockIdx.y, b = blockIdx.z;
    const size_t base = ((size_t)b * C_ + h * KC_) * T_;
    const float* Qb = Q + base;
    const float* Kb = Kp + base;
    const float* Vb = V + base;

    const int tid = threadIdx.x;
    const int tx = tid & 15, ty = tid >> 4;

    for (int idx = tid; idx < D*BR; idx += 256) {
        int d = idx / BR, r = idx - d * BR;
        Qs[idx] = Qb[(size_t)d * T_ + t0 + r] * SCALE_;
    }
    __syncthreads();
    // q · erk  (scaled q already)
    for (int idx = tid; idx < BR * 9; idx += 256) {
        int r = idx / 9, dd = idx - r * 9;
        float s = 0.f;
        #pragma unroll 8
        for (int d = 0; d < D; d++) s = fmaf(Qs[d*BR + r], erk[dd*KC_ + d], s);
        qr[idx] = s;
    }

    float m_i[4], l_i[4];
    ull oa[4][3];
    #pragma unroll
    for (int i = 0; i < 4; i++) {
        m_i[i] = -1e30f; l_i[i] = 0.f;
        #pragma unroll
        for (int j = 0; j < 3; j++) oa[i][j] = 0ull;
    }

    for (int s0 = 0; s0 < T_; s0 += BC) {
        __syncthreads();  // previous phase done reading Ks/Vs/Ps
        for (int idx = tid; idx < D*BC; idx += 256) {
            int d = idx / BC, c = idx - d * BC;
            Ks[d*BC + c] = Kb[(size_t)d * T_ + s0 + c];
            Vs[c*VSTR + d] = Vb[(size_t)d * T_ + s0 + c];
        }
        __syncthreads();

        // S = Q K^T  (packed pairs along cols)
        ull sc2[4][2] = {};
        #pragma unroll 4
        for (int d = 0; d < D; d++) {
            float4 a4 = *(const float4*)&Qs[d*BR + ty*4];
            float4 b4 = *(const float4*)&Ks[d*BC + tx*4];
            ull bp0 = fpack(b4.x, b4.y), bp1 = fpack(b4.z, b4.w);
            float av[4] = {a4.x, a4.y, a4.z, a4.w};
            #pragma unroll
            for (int i = 0; i < 4; i++) {
                ull ad = fdup(av[i]);
                sc2[i][0] = ffma2(ad, bp0, sc2[i][0]);
                sc2[i][1] = ffma2(ad, bp1, sc2[i][1]);
            }
        }
        float sc[4][4];
        #pragma unroll
        for (int i = 0; i < 4; i++) {
            float2 lo = funpack(sc2[i][0]), hi = funpack(sc2[i][1]);
            sc[i][0] = lo.x; sc[i][1] = lo.y; sc[i][2] = hi.x; sc[i][3] = hi.y;
        }

        // relative-K band (only near-diagonal tiles)
        if (s0 + BC + 4 > t0 && s0 < t0 + BR + 5) {
            #pragma unroll
            for (int i = 0; i < 4; i++)
                #pragma unroll
                for (int j = 0; j < 4; j++) {
                    int delta = (s0 + tx*4 + j) - (t0 + ty*4 + i);
                    if (delta >= -4 && delta <= 4)
                        sc[i][j] += qr[(ty*4 + i)*9 + delta + 4];
                }
        }

        // online softmax (row reduce across 16 tx lanes)
        #pragma unroll
        for (int i = 0; i < 4; i++) {
            float mx = fmaxf(fmaxf(sc[i][0], sc[i][1]), fmaxf(sc[i][2], sc[i][3]));
            #pragma unroll
            for (int off = 8; off; off >>= 1)
                mx = fmaxf(mx, __shfl_xor_sync(0xffffffffu, mx, off));
            float mn = fmaxf(m_i[i], mx);
            float al = __expf(m_i[i] - mn);
            float p0 = __expf(sc[i][0] - mn), p1 = __expf(sc[i][1] - mn);
            float p2 = __expf(sc[i][2] - mn), p3 = __expf(sc[i][3] - mn);
            *(float4*)&Ps[(ty*4 + i)*BC + tx*4] = make_float4(p0, p1, p2, p3);
            float rs = p0 + p1 + p2 + p3;
            #pragma unroll
            for (int off = 8; off; off >>= 1)
                rs += __shfl_xor_sync(0xffffffffu, rs, off);
            l_i[i] = l_i[i] * al + rs;
            m_i[i] = mn;
            ull al2 = fdup(al);
            #pragma unroll
            for (int j = 0; j < 3; j++) oa[i][j] = fmul2(oa[i][j], al2);
        }
        __syncthreads();

        // O += P @ V  (thread owns rows ty*4+i, d-cols tx*6 .. +5 as 3 pairs)
        #pragma unroll 2
        for (int s = 0; s < BC; s++) {
            ull pd[4];
            #pragma unroll
            for (int i = 0; i < 4; i++) pd[i] = fdup(Ps[(ty*4 + i)*BC + s]);
            const float* vrow = &Vs[s*VSTR + tx*6];
            ull v0 = *(const ull*)(vrow);
            ull v1 = *(const ull*)(vrow + 2);
            ull v2 = *(const ull*)(vrow + 4);
            #pragma unroll
            for (int i = 0; i < 4; i++) {
                oa[i][0] = ffma2(pd[i], v0, oa[i][0]);
                oa[i][1] = ffma2(pd[i], v1, oa[i][1]);
                oa[i][2] = ffma2(pd[i], v2, oa[i][2]);
            }
        }
    }
    __syncthreads();

    // normalize + stage through smem for coalesced store
    #pragma unroll
    for (int i = 0; i < 4; i++) {
        float inv = 1.f / l_i[i];
        #pragma unroll
        for (int j = 0; j < 3; j++) {
            float2 p = funpack(oa[i][j]);
            Qs[(tx*6 + j*2    )*BR + ty*4 + i] = p.x * inv;
            Qs[(tx*6 + j*2 + 1)*BR + ty*4 + i] = p.y * inv;
        }
    }
    if (tx == 0) {
        #pragma unroll
        for (int i = 0; i < 4; i++) {
            int t = t0 + ty*4 + i;
            Mo[((size_t)b*H_ + h)*T_ + t] = m_i[i];
            Lo[((size_t)b*H_ + h)*T_ + t] = l_i[i];
        }
    }
    __syncthreads();
    float* Ob = O + base;
    for (int idx = tid; idx < D*BR; idx += 256) {
        int d = idx / BR, r = idx - d * BR;
        Ob[(size_t)d * T_ + t0 + r] = Qs[idx];
    }
}

// ---------------- relative-V band correction ----------------
__global__ __launch_bounds__(256) void k_relv(
    const float* __restrict__ Q, const float* __restrict__ Kp,
    const float* __restrict__ erk, const float* __restrict__ erv,
    const float* __restrict__ Mo, const float* __restrict__ Lo,
    float* __restrict__ O)
{
    __shared__ float Qt[96*32];
    __shared__ float Kt[96*40];
    __shared__ float ek[9*96], ev[9*96];

    const int t0 = blockIdx.x * 32;
    const int h = blockIdx.y, b = blockIdx.z;
    const size_t base = ((size_t)b * C_ + h * KC_) * T_;
    const int tid = threadIdx.x;

    for (int idx = tid; idx < 96*32; idx += 256) {
        int d = idx / 32, u = idx - d * 32;
        Qt[idx] = Q[base + (size_t)d * T_ + t0 + u] * SCALE_;
    }
    for (int idx = tid; idx < 96*40; idx += 256) {
        int d = idx / 40, u = idx - d * 40;
        int t = t0 - 4 + u;
        Kt[idx] = (t >= 0 && t < T_) ? Kp[base + (size_t)d * T_ + t] : 0.f;
    }
    for (int idx = tid; idx < 9*96; idx += 256) { ek[idx] = erk[idx]; ev[idx] = erv[idx]; }
    __syncthreads();

    const int tx = tid & 31, g = tid >> 5;     // 32 t-lanes x 8 d-groups
    const int t = t0 + tx;
    const float m = Mo[((size_t)b*H_ + h)*T_ + t];
    const float invl = 1.f / Lo[((size_t)b*H_ + h)*T_ + t];

    float p[9];
    #pragma unroll
    for (int dd = 0; dd < 9; dd++) {
        int s = t + dd - 4;
        if (s < 0 || s >= T_) { p[dd] = 0.f; continue; }
        float sc = 0.f;
        #pragma unroll 8
        for (int d = 0; d < 96; d++)
            sc = fmaf(Qt[d*32 + tx], Kt[d*40 + tx + dd] + ek[dd*96 + d], sc);
        p[dd] = __expf(sc - m) * invl;
    }
    #pragma unroll
    for (int jd = 0; jd < 12; jd++) {
        int d = g * 12 + jd;
        float add = 0.f;
        #pragma unroll
        for (int dd = 0; dd < 9; dd++) add = fmaf(p[dd], ev[dd*96 + d], add);
        O[base + (size_t)d * T_ + t] += add;
    }
}

// ---------------- fused residual-add + channel LayerNorm ----------------
__global__ __launch_bounds__(256) void k_addln(
    float* __restrict__ X, const float* __restrict__ R,
    const float* __restrict__ gg, const float* __restrict__ be)
{
    const int tx = threadIdx.x, ty = threadIdx.y;
    const int t = blockIdx.x * 32 + tx;
    const int b = blockIdx.y;

    float vals[24];
    float s = 0.f, sq = 0.f;
    #pragma unroll
    for (int k = 0; k < 24; k++) {
        int c = ty + k * 8;
        size_t idx = ((size_t)b * C_ + c) * T_ + t;
        float v = X[idx] + R[idx];
        vals[k] = v; s += v; sq += v * v;
    }
    __shared__ float ss[8][33], sg[8][33];
    ss[ty][tx] = s; sg[ty][tx] = sq;
    __syncthreads();
    if (ty == 0) {
        float a = 0.f, q = 0.f;
        #pragma unroll
        for (int k = 0; k < 8; k++) { a += ss[k][tx]; q += sg[k][tx]; }
        ss[0][tx] = a; sg[0][tx] = q;
    }
    __syncthreads();
    const float mean = ss[0][tx] * (1.f / C_);
    const float var  = sg[0][tx] * (1.f / C_) - mean * mean;
    const float rstd = rsqrtf(var + EPS_);
    #pragma unroll
    for (int k = 0; k < 24; k++) {
        int c = ty + k * 8;
        size_t idx = ((size_t)b * C_ + c) * T_ + t;
        X[idx] = (vals[k] - mean) * rstd * gg[c] + be[c];
    }
}

// 3-operand variant for split-K conv2: x = LN(x + r1 + r2)
__global__ __launch_bounds__(256) void k_addln3(
    float* __restrict__ X, const float* __restrict__ R1, const float* __restrict__ R2,
    const float* __restrict__ gg, const float* __restrict__ be)
{
    const int tx = threadIdx.x, ty = threadIdx.y;
    const int t = blockIdx.x * 32 + tx;
    const int b = blockIdx.y;

    float vals[24];
    float s = 0.f, sq = 0.f;
    #pragma unroll
    for (int k = 0; k < 24; k++) {
        int c = ty + k * 8;
        size_t idx = ((size_t)b * C_ + c) * T_ + t;
        float v = X[idx] + R1[idx] + R2[idx];
        vals[k] = v; s += v; sq += v * v;
    }
    __shared__ float ss[8][33], sg[8][33];
    ss[ty][tx] = s; sg[ty][tx] = sq;
    __syncthreads();
    if (ty == 0) {
        float a = 0.f, q = 0.f;
        #pragma unroll
        for (int k = 0; k < 8; k++) { a += ss[k][tx]; q += sg[k][tx]; }
        ss[0][tx] = a; sg[0][tx] = q;
    }
    __syncthreads();
    const float mean = ss[0][tx] * (1.f / C_);
    const float var  = sg[0][tx] * (1.f / C_) - mean * mean;
    const float rstd = rsqrtf(var + EPS_);
    #pragma unroll
    for (int k = 0; k < 24; k++) {
        int c = ty + k * 8;
        size_t idx = ((size_t)b * C_ + c) * T_ + t;
        X[idx] = (vals[k] - mean) * rstd * gg[c] + be[c];
    }
}

// ---------------- launcher ----------------
extern "C" void kernel_launch(void* const* d_in, const int* in_sizes, int n_in,
                              void* d_out, int out_size)
{
    (void)in_sizes; (void)n_in; (void)out_size;
    const float* x   = (const float*)d_in[0];
    const float* msk = (const float*)d_in[1];
    const float* Wq  = (const float*)d_in[2];
    const float* bq  = (const float*)d_in[3];
    const float* Wk  = (const float*)d_in[4];
    const float* bk  = (const float*)d_in[5];
    const float* Wv  = (const float*)d_in[6];
    const float* bv  = (const float*)d_in[7];
    const float* Wo  = (const float*)d_in[8];
    const float* bo  = (const float*)d_in[9];
    const float* erk = (const float*)d_in[10];
    const float* erv = (const float*)d_in[11];
    const float* g1  = (const float*)d_in[12];
    const float* be1 = (const float*)d_in[13];
    const float* fw1 = (const float*)d_in[14];
    const float* fb1 = (const float*)d_in[15];
    const float* fw2 = (const float*)d_in[16];
    const float* fb2 = (const float*)d_in[17];
    const float* g2  = (const float*)d_in[18];
    const float* be2 = (const float*)d_in[19];

    float *xb, *qb, *kb, *vb, *ab, *tb, *fb, *mb, *lb;
    cudaGetSymbolAddress((void**)&xb, g_x);
    cudaGetSymbolAddress((void**)&qb, g_q);
    cudaGetSymbolAddress((void**)&kb, g_k);
    cudaGetSymbolAddress((void**)&vb, g_v);
    cudaGetSymbolAddress((void**)&ab, g_a);
    cudaGetSymbolAddress((void**)&tb, g_t);
    cudaGetSymbolAddress((void**)&fb, g_f);
    cudaGetSymbolAddress((void**)&mb, g_m);
    cudaGetSymbolAddress((void**)&lb, g_l);

    constexpr int FLASH_SMEM = (96*64 + 96*64 + 64*98 + 64*64 + 64*9) * 4;
    cudaFuncSetAttribute(k_flash, cudaFuncAttributeMaxDynamicSharedMemorySize, FLASH_SMEM);

    k_maskmul<<<(B_*C_*T_ + 255)/256, 256>>>(x, msk, xb);

    for (int i = 0; i < L_; i++) {
        // fused QKV projections: 1152 blocks, identical BN=64 microkernel
        k_qkv<<<dim3(T_/64, 9, B_), 128>>>(
            xb,
            Wq + (size_t)i*C_*C_, bq + i*C_, qb,
            Wk + (size_t)i*C_*C_, bk + i*C_, kb,
            Wv + (size_t)i*C_*C_, bv + i*C_, vb);

        k_flash<<<dim3(T_/64, H_, B_), 256, FLASH_SMEM>>>(
            qb, kb, vb, erk + (size_t)i*9*KC_, ab, mb, lb);
        k_relv<<<dim3(T_/32, H_, B_), 256>>>(
            qb, kb, erk + (size_t)i*9*KC_, erv + (size_t)i*9*KC_, mb, lb, ab);

        k_gemm<1><<<dim3(T_/64, C_/64, B_), 128>>>(
            ab, Wo + (size_t)i*C_*C_, bo + i*C_, tb, C_, C_, 0);
        k_addln<<<dim3(T_/32, B_), dim3(32, 8)>>>(xb, tb, g1 + i*C_, be1 + i*C_);

        k_gemm<3><<<dim3(T_/64, FC_/64, B_), 128>>>(
            xb, fw1 + (size_t)i*FC_*C_*3, fb1 + i*FC_, fb, FC_, C_, 1);

        // split-K conv2: 768 blocks, two Cin halves -> partials in tb, ab
        k_conv2split<<<dim3(T_/64, 6, B_), 128>>>(
            fb, fw2 + (size_t)i*C_*FC_*3, fb2 + i*C_, tb, ab);
        k_addln3<<<dim3(T_/32, B_), dim3(32, 8)>>>(xb, tb, ab, g2 + i*C_, be2 + i*C_);
    }

    k_maskmul<<<(B_*C_*T_ + 255)/256, 256>>>(xb, msk, (float*)d_out);
}

// round 8
// speedup vs baseline: 2.2280x; 1.2216x over previous
#include <cuda_runtime.h>
#include <math.h>

// ---------------- problem constants ----------------
#define B_  4
#define C_  192
#define T_  2048
#define H_  2
#define KC_ 96
#define FC_ 768
#define L_  6
#define SCALE_ 0.10206207261596577f   // 96^-0.5
#define EPS_ 1e-5f

// ---------------- packed f32x2 helpers (Blackwell FFMA2, used by flash) ----------------
typedef unsigned long long ull;
__device__ __forceinline__ ull ffma2(ull a, ull b, ull c) {
    ull d; asm("fma.rn.f32x2 %0, %1, %2, %3;" : "=l"(d) : "l"(a), "l"(b), "l"(c));
    return d;
}
__device__ __forceinline__ ull fmul2(ull a, ull b) {
    ull d; asm("mul.rn.f32x2 %0, %1, %2;" : "=l"(d) : "l"(a), "l"(b));
    return d;
}
__device__ __forceinline__ ull fdup(float x) {
    ull r; asm("mov.b64 %0, {%1, %2};" : "=l"(r) : "f"(x), "f"(x));
    return r;
}
__device__ __forceinline__ ull fpack(float lo, float hi) {
    ull r; asm("mov.b64 %0, {%1, %2};" : "=l"(r) : "f"(lo), "f"(hi));
    return r;
}
__device__ __forceinline__ float2 funpack(ull v) {
    float2 f; asm("mov.b64 {%0, %1}, %2;" : "=f"(f.x), "=f"(f.y) : "l"(v));
    return f;
}

// ---------------- tf32 mma.sync helpers ----------------
__device__ __forceinline__ float to_tf32(float x) {
    unsigned r; asm("cvt.rna.tf32.f32 %0, %1;" : "=r"(r) : "f"(x));
    return __uint_as_float(r);
}
__device__ __forceinline__ void mma_tf32(float* d, const float* a, const float* b) {
    asm("mma.sync.aligned.m16n8k8.row.col.f32.tf32.tf32.f32 "
        "{%0,%1,%2,%3}, {%4,%5,%6,%7}, {%8,%9}, {%0,%1,%2,%3};"
        : "+f"(d[0]), "+f"(d[1]), "+f"(d[2]), "+f"(d[3])
        : "r"(__float_as_uint(a[0])), "r"(__float_as_uint(a[1])),
          "r"(__float_as_uint(a[2])), "r"(__float_as_uint(a[3])),
          "r"(__float_as_uint(b[0])), "r"(__float_as_uint(b[1])));
}

// ---------------- scratch (no allocations allowed) ----------------
__device__ float g_x[B_*C_*T_];
__device__ float g_q[B_*C_*T_];
__device__ float g_k[B_*C_*T_];
__device__ float g_v[B_*C_*T_];
__device__ float g_a[B_*C_*T_];
__device__ float g_t[B_*C_*T_];
__device__ float g_f[B_*FC_*T_];
__device__ float g_m[B_*H_*T_];
__device__ float g_l[B_*H_*T_];

// ---------------- elementwise mask multiply ----------------
__global__ void k_maskmul(const float* __restrict__ in, const float* __restrict__ msk,
                          float* __restrict__ out)
{
    int idx = blockIdx.x * blockDim.x + threadIdx.x;
    if (idx >= B_*C_*T_) return;
    int b = idx / (C_*T_);
    int t = idx % T_;
    out[idx] = in[idx] * msk[b*T_ + t];
}

// ---------------- tensor-core GEMM/conv body (tf32 mma.sync) ----------------
// Y[o, t0..t0+64) = bias?[o] + sum_{c in [c_begin,c_end), kw} W[o,c,kw]*X[c, t+kw-pad]
// 256 threads = 8 warps in 2(M)x4(N) grid; block tile 64x64; warp tile 32x16.
// Fragments: m16n8k8 tf32, A=W (row-major), B=X (col-major k x n).
template<int KW>
__device__ __forceinline__ void mma_body(
    const float* __restrict__ Xb, const float* __restrict__ Wg,
    const float* __restrict__ bias, float* __restrict__ Yb,
    int Cin, int relu, int m0, int t0, int c_begin, int c_end)
{
    constexpr int BM = 64, BN = 64, BK = 32;
    constexpr int PADW = (KW - 1) / 2;
    constexpr int XV = BN + KW - 1;      // valid halo width
    constexpr int ST = 72;               // smem stride: 72 mod 32 == 8 -> conflict-free frags

    __shared__ float Ws[KW][BK][ST];     // tf32-converted W, [kw][c][o]
    __shared__ float Xs[BK][ST];         // tf32-converted X, [c][u]

    const int tid  = threadIdx.x;
    const int lane = tid & 31, wid = tid >> 5;
    const int wm = wid >> 2, wn = wid & 3;     // warp grid 2 x 4
    const int g = lane >> 2, tig = lane & 3;   // mma lane decomposition
    const int mb = wm * 32, nb = wn * 16;

    float acc[2][2][4] = {};   // [m-frag][n-frag][d0..d3]

    for (int c0 = c_begin; c0 < c_end; c0 += BK) {
        for (int idx = tid; idx < BM*BK*KW; idx += 256) {
            int o  = idx / (BK*KW);
            int ck = idx - o * (BK*KW);
            int c  = ck / KW, k = ck - c * KW;
            Ws[k][c][o] = to_tf32(Wg[((size_t)(m0 + o) * Cin + c0 + c) * KW + k]);
        }
        for (int idx = tid; idx < BK*XV; idx += 256) {
            int c = idx / XV, u = idx - c * XV;
            int t = t0 - PADW + u;
            Xs[c][u] = (t >= 0 && t < T_) ? to_tf32(Xb[(size_t)(c0 + c) * T_ + t]) : 0.f;
        }
        __syncthreads();

        #pragma unroll
        for (int kk = 0; kk < BK; kk += 8) {
            #pragma unroll
            for (int kw = 0; kw < KW; kw++) {
                float a[2][4], b[2][2];
                #pragma unroll
                for (int i = 0; i < 2; i++) {
                    a[i][0] = Ws[kw][kk + tig    ][mb + i*16 + g    ];
                    a[i][1] = Ws[kw][kk + tig    ][mb + i*16 + g + 8];
                    a[i][2] = Ws[kw][kk + tig + 4][mb + i*16 + g    ];
                    a[i][3] = Ws[kw][kk + tig + 4][mb + i*16 + g + 8];
                }
                #pragma unroll
                for (int j = 0; j < 2; j++) {
                    b[j][0] = Xs[kk + tig    ][nb + j*8 + g + kw];
                    b[j][1] = Xs[kk + tig + 4][nb + j*8 + g + kw];
                }
                #pragma unroll
                for (int i = 0; i < 2; i++)
                    #pragma unroll
                    for (int j = 0; j < 2; j++)
                        mma_tf32(acc[i][j], a[i], b[j]);
            }
        }
        __syncthreads();
    }

    #pragma unroll
    for (int i = 0; i < 2; i++) {
        int o0 = m0 + mb + i*16 + g;
        float b0 = bias ? bias[o0]     : 0.f;
        float b8 = bias ? bias[o0 + 8] : 0.f;
        #pragma unroll
        for (int j = 0; j < 2; j++) {
            int t = t0 + nb + j*8 + 2*tig;
            float2 v0 = make_float2(acc[i][j][0] + b0, acc[i][j][1] + b0);
            float2 v1 = make_float2(acc[i][j][2] + b8, acc[i][j][3] + b8);
            if (relu) {
                v0.x = fmaxf(v0.x, 0.f); v0.y = fmaxf(v0.y, 0.f);
                v1.x = fmaxf(v1.x, 0.f); v1.y = fmaxf(v1.y, 0.f);
            }
            *reinterpret_cast<float2*>(&Yb[(size_t)o0       * T_ + t]) = v0;
            *reinterpret_cast<float2*>(&Yb[(size_t)(o0 + 8) * T_ + t]) = v1;
        }
    }
}

template<int KW>
__global__ __launch_bounds__(256) void k_mma(
    const float* __restrict__ X, const float* __restrict__ Wg,
    const float* __restrict__ bias, float* __restrict__ Y,
    int M, int Cin, int relu)
{
    const int b = blockIdx.z;
    mma_body<KW>(X + (size_t)b * Cin * T_, Wg, bias, Y + (size_t)b * M * T_,
                 Cin, relu, blockIdx.y * 64, blockIdx.x * 64, 0, Cin);
}

// fused Q/K/V projection: grid.y = 9 -> (matrix, m-tile)
__global__ __launch_bounds__(256) void k_qkv(
    const float* __restrict__ X,
    const float* __restrict__ Wq, const float* __restrict__ bq, float* __restrict__ Yq,
    const float* __restrict__ Wk, const float* __restrict__ bk, float* __restrict__ Yk,
    const float* __restrict__ Wv, const float* __restrict__ bv, float* __restrict__ Yv)
{
    const int b = blockIdx.z;
    const int mat = blockIdx.y / 3;
    const int m0  = (blockIdx.y % 3) * 64;
    const float *W, *bi; float *Y;
    if (mat == 0)      { W = Wq; bi = bq; Y = Yq; }
    else if (mat == 1) { W = Wk; bi = bk; Y = Yk; }
    else               { W = Wv; bi = bv; Y = Yv; }
    mma_body<1>(X + (size_t)b * C_ * T_, W, bi, Y + (size_t)b * C_ * T_,
                C_, 0, m0, blockIdx.x * 64, 0, C_);
}

// split-K conv2: grid.y = 6 -> (half, m-tile). half 0 covers Cin [0,384) + bias,
// half 1 covers [384,768), no bias. Partials summed in k_addln3.
__global__ __launch_bounds__(256) void k_conv2split(
    const float* __restrict__ X, const float* __restrict__ Wg,
    const float* __restrict__ bias, float* __restrict__ Y1, float* __restrict__ Y2)
{
    const int b = blockIdx.z;
    const int half = blockIdx.y / 3;
    const int m0   = (blockIdx.y % 3) * 64;
    float* Y = half ? Y2 : Y1;
    mma_body<3>(X + (size_t)b * FC_ * T_, Wg, half ? nullptr : bias,
                Y + (size_t)b * C_ * T_, FC_, 0, m0, blockIdx.x * 64,
                half * (FC_/2), (half + 1) * (FC_/2));
}

// ---------------- flash attention with relative-K band (FFMA2) ----------------
__global__ __launch_bounds__(256) void k_flash(
    const float* __restrict__ Q, const float* __restrict__ Kp, const float* __restrict__ V,
    const float* __restrict__ erk, float* __restrict__ O,
    float* __restrict__ Mo, float* __restrict__ Lo)
{
    constexpr int BR = 64, BC = 64, D = 96, VSTR = 98; // V stored [s][d], padded stride
    extern __shared__ float sm[];
    float* Qs = sm;                 // D*BR     [d][r]
    float* Ks = Qs + D*BR;          // D*BC     [d][c]
    float* Vs = Ks + D*BC;          // BC*VSTR  [s][d]
    float* Ps = Vs + BC*VSTR;       // BR*BC
    float* qr = Ps + BR*BC;         // BR*9

    const int t0 = blockIdx.x * BR;
    const int h = blockIdx.y, b = blockIdx.z;
    const size_t base = ((size_t)b * C_ + h * KC_) * T_;
    const float* Qb = Q + base;
    const float* Kb = Kp + base;
    const float* Vb = V + base;

    const int tid = threadIdx.x;
    const int tx = tid & 15, ty = tid >> 4;

    for (int idx = tid; idx < D*BR; idx += 256) {
        int d = idx / BR, r = idx - d * BR;
        Qs[idx] = Qb[(size_t)d * T_ + t0 + r] * SCALE_;
    }
    __syncthreads();
    // q · erk  (scaled q already)
    for (int idx = tid; idx < BR * 9; idx += 256) {
        int r = idx / 9, dd = idx - r * 9;
        float s = 0.f;
        #pragma unroll 8
        for (int d = 0; d < D; d++) s = fmaf(Qs[d*BR + r], erk[dd*KC_ + d], s);
        qr[idx] = s;
    }

    float m_i[4], l_i[4];
    ull oa[4][3];
    #pragma unroll
    for (int i = 0; i < 4; i++) {
        m_i[i] = -1e30f; l_i[i] = 0.f;
        #pragma unroll
        for (int j = 0; j < 3; j++) oa[i][j] = 0ull;
    }

    for (int s0 = 0; s0 < T_; s0 += BC) {
        __syncthreads();  // previous phase done reading Ks/Vs/Ps
        for (int idx = tid; idx < D*BC; idx += 256) {
            int d = idx / BC, c = idx - d * BC;
            Ks[d*BC + c] = Kb[(size_t)d * T_ + s0 + c];
            Vs[c*VSTR + d] = Vb[(size_t)d * T_ + s0 + c];
        }
        __syncthreads();

        // S = Q K^T  (packed pairs along cols)
        ull sc2[4][2] = {};
        #pragma unroll 4
        for (int d = 0; d < D; d++) {
            float4 a4 = *(const float4*)&Qs[d*BR + ty*4];
            float4 b4 = *(const float4*)&Ks[d*BC + tx*4];
            ull bp0 = fpack(b4.x, b4.y), bp1 = fpack(b4.z, b4.w);
            float av[4] = {a4.x, a4.y, a4.z, a4.w};
            #pragma unroll
            for (int i = 0; i < 4; i++) {
                ull ad = fdup(av[i]);
                sc2[i][0] = ffma2(ad, bp0, sc2[i][0]);
                sc2[i][1] = ffma2(ad, bp1, sc2[i][1]);
            }
        }
        float sc[4][4];
        #pragma unroll
        for (int i = 0; i < 4; i++) {
            float2 lo = funpack(sc2[i][0]), hi = funpack(sc2[i][1]);
            sc[i][0] = lo.x; sc[i][1] = lo.y; sc[i][2] = hi.x; sc[i][3] = hi.y;
        }

        // relative-K band (only near-diagonal tiles)
        if (s0 + BC + 4 > t0 && s0 < t0 + BR + 5) {
            #pragma unroll
            for (int i = 0; i < 4; i++)
                #pragma unroll
                for (int j = 0; j < 4; j++) {
                    int delta = (s0 + tx*4 + j) - (t0 + ty*4 + i);
                    if (delta >= -4 && delta <= 4)
                        sc[i][j] += qr[(ty*4 + i)*9 + delta + 4];
                }
        }

        // online softmax (row reduce across 16 tx lanes)
        #pragma unroll
        for (int i = 0; i < 4; i++) {
            float mx = fmaxf(fmaxf(sc[i][0], sc[i][1]), fmaxf(sc[i][2], sc[i][3]));
            #pragma unroll
            for (int off = 8; off; off >>= 1)
                mx = fmaxf(mx, __shfl_xor_sync(0xffffffffu, mx, off));
            float mn = fmaxf(m_i[i], mx);
            float al = __expf(m_i[i] - mn);
            float p0 = __expf(sc[i][0] - mn), p1 = __expf(sc[i][1] - mn);
            float p2 = __expf(sc[i][2] - mn), p3 = __expf(sc[i][3] - mn);
            *(float4*)&Ps[(ty*4 + i)*BC + tx*4] = make_float4(p0, p1, p2, p3);
            float rs = p0 + p1 + p2 + p3;
            #pragma unroll
            for (int off = 8; off; off >>= 1)
                rs += __shfl_xor_sync(0xffffffffu, rs, off);
            l_i[i] = l_i[i] * al + rs;
            m_i[i] = mn;
            ull al2 = fdup(al);
            #pragma unroll
            for (int j = 0; j < 3; j++) oa[i][j] = fmul2(oa[i][j], al2);
        }
        __syncthreads();

        // O += P @ V  (thread owns rows ty*4+i, d-cols tx*6 .. +5 as 3 pairs)
        #pragma unroll 2
        for (int s = 0; s < BC; s++) {
            ull pd[4];
            #pragma unroll
            for (int i = 0; i < 4; i++) pd[i] = fdup(Ps[(ty*4 + i)*BC + s]);
            const float* vrow = &Vs[s*VSTR + tx*6];
            ull v0 = *(const ull*)(vrow);
            ull v1 = *(const ull*)(vrow + 2);
            ull v2 = *(const ull*)(vrow + 4);
            #pragma unroll
            for (int i = 0; i < 4; i++) {
                oa[i][0] = ffma2(pd[i], v0, oa[i][0]);
                oa[i][1] = ffma2(pd[i], v1, oa[i][1]);
                oa[i][2] = ffma2(pd[i], v2, oa[i][2]);
            }
        }
    }
    __syncthreads();

    // normalize + stage through smem for coalesced store
    #pragma unroll
    for (int i = 0; i < 4; i++) {
        float inv = 1.f / l_i[i];
        #pragma unroll
        for (int j = 0; j < 3; j++) {
            float2 p = funpack(oa[i][j]);
            Qs[(tx*6 + j*2    )*BR + ty*4 + i] = p.x * inv;
            Qs[(tx*6 + j*2 + 1)*BR + ty*4 + i] = p.y * inv;
        }
    }
    if (tx == 0) {
        #pragma unroll
        for (int i = 0; i < 4; i++) {
            int t = t0 + ty*4 + i;
            Mo[((size_t)b*H_ + h)*T_ + t] = m_i[i];
            Lo[((size_t)b*H_ + h)*T_ + t] = l_i[i];
        }
    }
    __syncthreads();
    float* Ob = O + base;
    for (int idx = tid; idx < D*BR; idx += 256) {
        int d = idx / BR, r = idx - d * BR;
        Ob[(size_t)d * T_ + t0 + r] = Qs[idx];
    }
}

// ---------------- relative-V band correction ----------------
__global__ __launch_bounds__(256) void k_relv(
    const float* __restrict__ Q, const float* __restrict__ Kp,
    const float* __restrict__ erk, const float* __restrict__ erv,
    const float* __restrict__ Mo, const float* __restrict__ Lo,
    float* __restrict__ O)
{
    __shared__ float Qt[96*32];
    __shared__ float Kt[96*40];
    __shared__ float ek[9*96], ev[9*96];

    const int t0 = blockIdx.x * 32;
    const int h = blockIdx.y, b = blockIdx.z;
    const size_t base = ((size_t)b * C_ + h * KC_) * T_;
    const int tid = threadIdx.x;

    for (int idx = tid; idx < 96*32; idx += 256) {
        int d = idx / 32, u = idx - d * 32;
        Qt[idx] = Q[base + (size_t)d * T_ + t0 + u] * SCALE_;
    }
    for (int idx = tid; idx < 96*40; idx += 256) {
        int d = idx / 40, u = idx - d * 40;
        int t = t0 - 4 + u;
        Kt[idx] = (t >= 0 && t < T_) ? Kp[base + (size_t)d * T_ + t] : 0.f;
    }
    for (int idx = tid; idx < 9*96; idx += 256) { ek[idx] = erk[idx]; ev[idx] = erv[idx]; }
    __syncthreads();

    const int tx = tid & 31, g = tid >> 5;     // 32 t-lanes x 8 d-groups
    const int t = t0 + tx;
    const float m = Mo[((size_t)b*H_ + h)*T_ + t];
    const float invl = 1.f / Lo[((size_t)b*H_ + h)*T_ + t];

    float p[9];
    #pragma unroll
    for (int dd = 0; dd < 9; dd++) {
        int s = t + dd - 4;
        if (s < 0 || s >= T_) { p[dd] = 0.f; continue; }
        float sc = 0.f;
        #pragma unroll 8
        for (int d = 0; d < 96; d++)
            sc = fmaf(Qt[d*32 + tx], Kt[d*40 + tx + dd] + ek[dd*96 + d], sc);
        p[dd] = __expf(sc - m) * invl;
    }
    #pragma unroll
    for (int jd = 0; jd < 12; jd++) {
        int d = g * 12 + jd;
        float add = 0.f;
        #pragma unroll
        for (int dd = 0; dd < 9; dd++) add = fmaf(p[dd], ev[dd*96 + d], add);
        O[base + (size_t)d * T_ + t] += add;
    }
}

// ---------------- fused residual-add + channel LayerNorm ----------------
__global__ __launch_bounds__(256) void k_addln(
    float* __restrict__ X, const float* __restrict__ R,
    const float* __restrict__ gg, const float* __restrict__ be)
{
    const int tx = threadIdx.x, ty = threadIdx.y;
    const int t = blockIdx.x * 32 + tx;
    const int b = blockIdx.y;

    float vals[24];
    float s = 0.f, sq = 0.f;
    #pragma unroll
    for (int k = 0; k < 24; k++) {
        int c = ty + k * 8;
        size_t idx = ((size_t)b * C_ + c) * T_ + t;
        float v = X[idx] + R[idx];
        vals[k] = v; s += v; sq += v * v;
    }
    __shared__ float ss[8][33], sg[8][33];
    ss[ty][tx] = s; sg[ty][tx] = sq;
    __syncthreads();
    if (ty == 0) {
        float a = 0.f, q = 0.f;
        #pragma unroll
        for (int k = 0; k < 8; k++) { a += ss[k][tx]; q += sg[k][tx]; }
        ss[0][tx] = a; sg[0][tx] = q;
    }
    __syncthreads();
    const float mean = ss[0][tx] * (1.f / C_);
    const float var  = sg[0][tx] * (1.f / C_) - mean * mean;
    const float rstd = rsqrtf(var + EPS_);
    #pragma unroll
    for (int k = 0; k < 24; k++) {
        int c = ty + k * 8;
        size_t idx = ((size_t)b * C_ + c) * T_ + t;
        X[idx] = (vals[k] - mean) * rstd * gg[c] + be[c];
    }
}

// 3-operand variant for split-K conv2: x = LN(x + r1 + r2)
__global__ __launch_bounds__(256) void k_addln3(
    float* __restrict__ X, const float* __restrict__ R1, const float* __restrict__ R2,
    const float* __restrict__ gg, const float* __restrict__ be)
{
    const int tx = threadIdx.x, ty = threadIdx.y;
    const int t = blockIdx.x * 32 + tx;
    const int b = blockIdx.y;

    float vals[24];
    float s = 0.f, sq = 0.f;
    #pragma unroll
    for (int k = 0; k < 24; k++) {
        int c = ty + k * 8;
        size_t idx = ((size_t)b * C_ + c) * T_ + t;
        float v = X[idx] + R1[idx] + R2[idx];
        vals[k] = v; s += v; sq += v * v;
    }
    __shared__ float ss[8][33], sg[8][33];
    ss[ty][tx] = s; sg[ty][tx] = sq;
    __syncthreads();
    if (ty == 0) {
        float a = 0.f, q = 0.f;
        #pragma unroll
        for (int k = 0; k < 8; k++) { a += ss[k][tx]; q += sg[k][tx]; }
        ss[0][tx] = a; sg[0][tx] = q;
    }
    __syncthreads();
    const float mean = ss[0][tx] * (1.f / C_);
    const float var  = sg[0][tx] * (1.f / C_) - mean * mean;
    const float rstd = rsqrtf(var + EPS_);
    #pragma unroll
    for (int k = 0; k < 24; k++) {
        int c = ty + k * 8;
        size_t idx = ((size_t)b * C_ + c) * T_ + t;
        X[idx] = (vals[k] - mean) * rstd * gg[c] + be[c];
    }
}

// ---------------- launcher ----------------
extern "C" void kernel_launch(void* const* d_in, const int* in_sizes, int n_in,
                              void* d_out, int out_size)
{
    (void)in_sizes; (void)n_in; (void)out_size;
    const float* x   = (const float*)d_in[0];
    const float* msk = (const float*)d_in[1];
    const float* Wq  = (const float*)d_in[2];
    const float* bq  = (const float*)d_in[3];
    const float* Wk  = (const float*)d_in[4];
    const float* bk  = (const float*)d_in[5];
    const float* Wv  = (const float*)d_in[6];
    const float* bv  = (const float*)d_in[7];
    const float* Wo  = (const float*)d_in[8];
    const float* bo  = (const float*)d_in[9];
    const float* erk = (const float*)d_in[10];
    const float* erv = (const float*)d_in[11];
    const float* g1  = (const float*)d_in[12];
    const float* be1 = (const float*)d_in[13];
    const float* fw1 = (const float*)d_in[14];
    const float* fb1 = (const float*)d_in[15];
    const float* fw2 = (const float*)d_in[16];
    const float* fb2 = (const float*)d_in[17];
    const float* g2  = (const float*)d_in[18];
    const float* be2 = (const float*)d_in[19];

    float *xb, *qb, *kb, *vb, *ab, *tb, *fb, *mb, *lb;
    cudaGetSymbolAddress((void**)&xb, g_x);
    cudaGetSymbolAddress((void**)&qb, g_q);
    cudaGetSymbolAddress((void**)&kb, g_k);
    cudaGetSymbolAddress((void**)&vb, g_v);
    cudaGetSymbolAddress((void**)&ab, g_a);
    cudaGetSymbolAddress((void**)&tb, g_t);
    cudaGetSymbolAddress((void**)&fb, g_f);
    cudaGetSymbolAddress((void**)&mb, g_m);
    cudaGetSymbolAddress((void**)&lb, g_l);

    constexpr int FLASH_SMEM = (96*64 + 96*64 + 64*98 + 64*64 + 64*9) * 4;
    cudaFuncSetAttribute(k_flash, cudaFuncAttributeMaxDynamicSharedMemorySize, FLASH_SMEM);

    k_maskmul<<<(B_*C_*T_ + 255)/256, 256>>>(x, msk, xb);

    for (int i = 0; i < L_; i++) {
        // fused QKV projections (tensor cores)
        k_qkv<<<dim3(T_/64, 9, B_), 256>>>(
            xb,
            Wq + (size_t)i*C_*C_, bq + i*C_, qb,
            Wk + (size_t)i*C_*C_, bk + i*C_, kb,
            Wv + (size_t)i*C_*C_, bv + i*C_, vb);

        k_flash<<<dim3(T_/64, H_, B_), 256, FLASH_SMEM>>>(
            qb, kb, vb, erk + (size_t)i*9*KC_, ab, mb, lb);
        k_relv<<<dim3(T_/32, H_, B_), 256>>>(
            qb, kb, erk + (size_t)i*9*KC_, erv + (size_t)i*9*KC_, mb, lb, ab);

        k_mma<1><<<dim3(T_/64, C_/64, B_), 256>>>(
            ab, Wo + (size_t)i*C_*C_, bo + i*C_, tb, C_, C_, 0);
        k_addln<<<dim3(T_/32, B_), dim3(32, 8)>>>(xb, tb, g1 + i*C_, be1 + i*C_);

        k_mma<3><<<dim3(T_/64, FC_/64, B_), 256>>>(
            xb, fw1 + (size_t)i*FC_*C_*3, fb1 + i*FC_, fb, FC_, C_, 1);

        // split-K conv2 (tensor cores): partials in tb, ab
        k_conv2split<<<dim3(T_/64, 6, B_), 256>>>(
            fb, fw2 + (size_t)i*C_*FC_*3, fb2 + i*C_, tb, ab);
        k_addln3<<<dim3(T_/32, B_), dim3(32, 8)>>>(xb, tb, ab, g2 + i*C_, be2 + i*C_);
    }

    k_maskmul<<<(B_*C_*T_ + 255)/256, 256>>>(xb, msk, (float*)d_out);
}

// round 10
// speedup vs baseline: 2.6803x; 1.2030x over previous
#include <cuda_runtime.h>
#include <math.h>

// ---------------- problem constants ----------------
#define B_  4
#define C_  192
#define T_  2048
#define H_  2
#define KC_ 96
#define FC_ 768
#define L_  6
#define SCALE_ 0.10206207261596577f   // 96^-0.5
#define EPS_ 1e-5f

// ---------------- tf32 mma.sync helpers ----------------
__device__ __forceinline__ float to_tf32(float x) {
    unsigned r; asm("cvt.rna.tf32.f32 %0, %1;" : "=r"(r) : "f"(x));
    return __uint_as_float(r);
}
__device__ __forceinline__ void mma_tf32(float* d, const float* a, const float* b) {
    asm("mma.sync.aligned.m16n8k8.row.col.f32.tf32.tf32.f32 "
        "{%0,%1,%2,%3}, {%4,%5,%6,%7}, {%8,%9}, {%0,%1,%2,%3};"
        : "+f"(d[0]), "+f"(d[1]), "+f"(d[2]), "+f"(d[3])
        : "r"(__float_as_uint(a[0])), "r"(__float_as_uint(a[1])),
          "r"(__float_as_uint(a[2])), "r"(__float_as_uint(a[3])),
          "r"(__float_as_uint(b[0])), "r"(__float_as_uint(b[1])));
}

// ---------------- scratch (no allocations allowed) ----------------
__device__ float g_x[B_*C_*T_];
__device__ float g_q[B_*C_*T_];
__device__ float g_k[B_*C_*T_];
__device__ float g_v[B_*C_*T_];
__device__ float g_a[B_*C_*T_];
__device__ float g_t[B_*C_*T_];
__device__ float g_f[B_*FC_*T_];
__device__ float g_m[B_*H_*T_];
__device__ float g_l[B_*H_*T_];

// ---------------- elementwise mask multiply ----------------
__global__ void k_maskmul(const float* __restrict__ in, const float* __restrict__ msk,
                          float* __restrict__ out)
{
    int idx = blockIdx.x * blockDim.x + threadIdx.x;
    if (idx >= B_*C_*T_) return;
    int b = idx / (C_*T_);
    int t = idx % T_;
    out[idx] = in[idx] * msk[b*T_ + t];
}

// ---------------- tensor-core GEMM/conv body (tf32 mma.sync) ----------------
template<int KW>
__device__ __forceinline__ void mma_body(
    const float* __restrict__ Xb, const float* __restrict__ Wg,
    const float* __restrict__ bias, float* __restrict__ Yb,
    int Cin, int relu, int m0, int t0, int c_begin, int c_end)
{
    constexpr int BM = 64, BN = 64, BK = 32;
    constexpr int PADW = (KW - 1) / 2;
    constexpr int XV = BN + KW - 1;
    constexpr int ST = 72;               // 72 mod 32 == 8 -> conflict-free frags

    __shared__ float Ws[KW][BK][ST];
    __shared__ float Xs[BK][ST];

    const int tid  = threadIdx.x;
    const int lane = tid & 31, wid = tid >> 5;
    const int wm = wid >> 2, wn = wid & 3;
    const int g = lane >> 2, tig = lane & 3;
    const int mb = wm * 32, nb = wn * 16;

    float acc[2][2][4] = {};

    for (int c0 = c_begin; c0 < c_end; c0 += BK) {
        for (int idx = tid; idx < BM*BK*KW; idx += 256) {
            int o  = idx / (BK*KW);
            int ck = idx - o * (BK*KW);
            int c  = ck / KW, k = ck - c * KW;
            Ws[k][c][o] = to_tf32(Wg[((size_t)(m0 + o) * Cin + c0 + c) * KW + k]);
        }
        for (int idx = tid; idx < BK*XV; idx += 256) {
            int c = idx / XV, u = idx - c * XV;
            int t = t0 - PADW + u;
            Xs[c][u] = (t >= 0 && t < T_) ? to_tf32(Xb[(size_t)(c0 + c) * T_ + t]) : 0.f;
        }
        __syncthreads();

        #pragma unroll
        for (int kk = 0; kk < BK; kk += 8) {
            #pragma unroll
            for (int kw = 0; kw < KW; kw++) {
                float a[2][4], b[2][2];
                #pragma unroll
                for (int i = 0; i < 2; i++) {
                    a[i][0] = Ws[kw][kk + tig    ][mb + i*16 + g    ];
                    a[i][1] = Ws[kw][kk + tig    ][mb + i*16 + g + 8];
                    a[i][2] = Ws[kw][kk + tig + 4][mb + i*16 + g    ];
                    a[i][3] = Ws[kw][kk + tig + 4][mb + i*16 + g + 8];
                }
                #pragma unroll
                for (int j = 0; j < 2; j++) {
                    b[j][0] = Xs[kk + tig    ][nb + j*8 + g + kw];
                    b[j][1] = Xs[kk + tig + 4][nb + j*8 + g + kw];
                }
                #pragma unroll
                for (int i = 0; i < 2; i++)
                    #pragma unroll
                    for (int j = 0; j < 2; j++)
                        mma_tf32(acc[i][j], a[i], b[j]);
            }
        }
        __syncthreads();
    }

    #pragma unroll
    for (int i = 0; i < 2; i++) {
        int o0 = m0 + mb + i*16 + g;
        float b0 = bias ? bias[o0]     : 0.f;
        float b8 = bias ? bias[o0 + 8] : 0.f;
        #pragma unroll
        for (int j = 0; j < 2; j++) {
            int t = t0 + nb + j*8 + 2*tig;
            float2 v0 = make_float2(acc[i][j][0] + b0, acc[i][j][1] + b0);
            float2 v1 = make_float2(acc[i][j][2] + b8, acc[i][j][3] + b8);
            if (relu) {
                v0.x = fmaxf(v0.x, 0.f); v0.y = fmaxf(v0.y, 0.f);
                v1.x = fmaxf(v1.x, 0.f); v1.y = fmaxf(v1.y, 0.f);
            }
            *reinterpret_cast<float2*>(&Yb[(size_t)o0       * T_ + t]) = v0;
            *reinterpret_cast<float2*>(&Yb[(size_t)(o0 + 8) * T_ + t]) = v1;
        }
    }
}

template<int KW>
__global__ __launch_bounds__(256) void k_mma(
    const float* __restrict__ X, const float* __restrict__ Wg,
    const float* __restrict__ bias, float* __restrict__ Y,
    int M, int Cin, int relu)
{
    const int b = blockIdx.z;
    mma_body<KW>(X + (size_t)b * Cin * T_, Wg, bias, Y + (size_t)b * M * T_,
                 Cin, relu, blockIdx.y * 64, blockIdx.x * 64, 0, Cin);
}

__global__ __launch_bounds__(256) void k_qkv(
    const float* __restrict__ X,
    const float* __restrict__ Wq, const float* __restrict__ bq, float* __restrict__ Yq,
    const float* __restrict__ Wk, const float* __restrict__ bk, float* __restrict__ Yk,
    const float* __restrict__ Wv, const float* __restrict__ bv, float* __restrict__ Yv)
{
    const int b = blockIdx.z;
    const int mat = blockIdx.y / 3;
    const int m0  = (blockIdx.y % 3) * 64;
    const float *W, *bi; float *Y;
    if (mat == 0)      { W = Wq; bi = bq; Y = Yq; }
    else if (mat == 1) { W = Wk; bi = bk; Y = Yk; }
    else               { W = Wv; bi = bv; Y = Yv; }
    mma_body<1>(X + (size_t)b * C_ * T_, W, bi, Y + (size_t)b * C_ * T_,
                C_, 0, m0, blockIdx.x * 64, 0, C_);
}

__global__ __launch_bounds__(256) void k_conv2split(
    const float* __restrict__ X, const float* __restrict__ Wg,
    const float* __restrict__ bias, float* __restrict__ Y1, float* __restrict__ Y2)
{
    const int b = blockIdx.z;
    const int half = blockIdx.y / 3;
    const int m0   = (blockIdx.y % 3) * 64;
    float* Y = half ? Y2 : Y1;
    mma_body<3>(X + (size_t)b * FC_ * T_, Wg, half ? nullptr : bias,
                Y + (size_t)b * C_ * T_, FC_, 0, m0, blockIdx.x * 64,
                half * (FC_/2), (half + 1) * (FC_/2));
}

// ---------------- flash attention: tf32 mma for QK^T and PV ----------------
// 128 threads = 4 warps; warp w owns rows t0+16w .. t0+16w+15 end-to-end.
// Fragment-friendly padded smem: bank = (4a+b) mod 32 bijective -> conflict-free.
__global__ __launch_bounds__(128) void k_flash(
    const float* __restrict__ Q, const float* __restrict__ Kp, const float* __restrict__ V,
    const float* __restrict__ erk, float* __restrict__ O,
    float* __restrict__ Mo, float* __restrict__ Lo)
{
    constexpr int BR = 64, BC = 64, D = 96;
    constexpr int QSTR = 100, KSTR = 68, VSTR = 100, PSTR = 68;
    extern __shared__ float sm[];
    float* Qs = sm;                  // BR*QSTR  [r][d] tf32(q*scale)
    float* Ks = Qs + BR*QSTR;        // D*KSTR   [d][s] tf32
    float* Vs = Ks + D*KSTR;         // BC*VSTR  [s][d] tf32
    float* Ps = Vs + BC*VSTR;        // BR*PSTR  [r][s] tf32 probabilities
    float* qr = Ps + BR*PSTR;        // BR*9

    const int t0 = blockIdx.x * BR;
    const int h = blockIdx.y, b = blockIdx.z;
    const size_t base = ((size_t)b * C_ + h * KC_) * T_;
    const float* Qb = Q + base;
    const float* Kb = Kp + base;
    const float* Vb = V + base;

    const int tid  = threadIdx.x;
    const int lane = tid & 31, w = tid >> 5;
    const int g = lane >> 2, tig = lane & 3;
    const int w16 = w * 16;

    // load Q tile: tf32(q * SCALE), [r][d]
    for (int idx = tid; idx < D*BR; idx += 128) {
        int d = idx / BR, r = idx - d * BR;
        Qs[r*QSTR + d] = to_tf32(Qb[(size_t)d * T_ + t0 + r] * SCALE_);
    }
    __syncthreads();
    // qr[r][dd] = q[r] . erk[dd]
    for (int idx = tid; idx < BR * 9; idx += 128) {
        int r = idx / 9, dd = idx - r * 9;
        float s = 0.f;
        #pragma unroll 8
        for (int d = 0; d < D; d++) s = fmaf(Qs[r*QSTR + d], erk[dd*KC_ + d], s);
        qr[idx] = s;
    }

    float m_i[2] = {-1e30f, -1e30f};
    float l_i[2] = {0.f, 0.f};
    float oa[12][4] = {};            // O accum: rows g/g+8, d = nf*8+2tig+{0,1}

    for (int s0 = 0; s0 < T_; s0 += BC) {
        __syncthreads();             // all warps done with Ks/Vs from prev tile
        for (int idx = tid; idx < D*BC; idx += 128) {
            int d = idx / BC, s = idx - d * BC;
            float kv = Kb[(size_t)d * T_ + s0 + s];
            float vv = Vb[(size_t)d * T_ + s0 + s];
            Ks[d*KSTR + s] = to_tf32(kv);
            Vs[s*VSTR + d] = to_tf32(vv);
        }
        __syncthreads();

        // ---- S = Q K^T : warp computes 16 x 64 (8 n-frags, 12 k-steps) ----
        float acc[8][4];
        #pragma unroll
        for (int nf = 0; nf < 8; nf++)
            #pragma unroll
            for (int e = 0; e < 4; e++) acc[nf][e] = 0.f;

        #pragma unroll
        for (int kk = 0; kk < D; kk += 8) {
            float a[4];
            a[0] = Qs[(w16 + g    )*QSTR + kk + tig    ];
            a[1] = Qs[(w16 + g + 8)*QSTR + kk + tig    ];
            a[2] = Qs[(w16 + g    )*QSTR + kk + tig + 4];
            a[3] = Qs[(w16 + g + 8)*QSTR + kk + tig + 4];
            #pragma unroll
            for (int nf = 0; nf < 8; nf++) {
                float bfr[2];
                bfr[0] = Ks[(kk + tig    )*KSTR + nf*8 + g];
                bfr[1] = Ks[(kk + tig + 4)*KSTR + nf*8 + g];
                mma_tf32(acc[nf], a, bfr);
            }
        }

        // ---- relative-K band (near-diagonal tiles only) ----
        if (s0 + BC + 4 > t0 && s0 < t0 + BR + 5) {
            #pragma unroll
            for (int nf = 0; nf < 8; nf++)
                #pragma unroll
                for (int e = 0; e < 2; e++) {
                    int col = s0 + nf*8 + 2*tig + e;
                    int r0 = t0 + w16 + g;
                    int d0 = col - r0;
                    if (d0 >= -4 && d0 <= 4) acc[nf][e]     += qr[(w16 + g)*9 + d0 + 4];
                    int d1 = col - (r0 + 8);
                    if (d1 >= -4 && d1 <= 4) acc[nf][e + 2] += qr[(w16 + g + 8)*9 + d1 + 4];
                }
        }

        // ---- online softmax per row (rows g and g+8; reduce over tig group) ----
        #pragma unroll
        for (int i = 0; i < 2; i++) {
            float mx = -1e30f;
            #pragma unroll
            for (int nf = 0; nf < 8; nf++)
                mx = fmaxf(mx, fmaxf(acc[nf][2*i], acc[nf][2*i + 1]));
            mx = fmaxf(mx, __shfl_xor_sync(0xffffffffu, mx, 1));
            mx = fmaxf(mx, __shfl_xor_sync(0xffffffffu, mx, 2));
            float mn = fmaxf(m_i[i], mx);
            float al = __expf(m_i[i] - mn);
            float rs = 0.f;
            int row = w16 + g + 8*i;
            #pragma unroll
            for (int nf = 0; nf < 8; nf++) {
                float p0 = to_tf32(__expf(acc[nf][2*i    ] - mn));
                float p1 = to_tf32(__expf(acc[nf][2*i + 1] - mn));
                *reinterpret_cast<float2*>(&Ps[row*PSTR + nf*8 + 2*tig]) = make_float2(p0, p1);
                rs += p0 + p1;
            }
            rs += __shfl_xor_sync(0xffffffffu, rs, 1);
            rs += __shfl_xor_sync(0xffffffffu, rs, 2);
            l_i[i] = l_i[i] * al + rs;
            m_i[i] = mn;
            #pragma unroll
            for (int nf = 0; nf < 12; nf++) {
                oa[nf][2*i] *= al; oa[nf][2*i + 1] *= al;
            }
        }
        __syncwarp();                // P rows are warp-private; warp-scope fence

        // ---- O += P @ V : 12 n-frags over d, 8 k-steps over s ----
        #pragma unroll
        for (int kk = 0; kk < BC; kk += 8) {
            float pa[4];
            pa[0] = Ps[(w16 + g    )*PSTR + kk + tig    ];
            pa[1] = Ps[(w16 + g + 8)*PSTR + kk + tig    ];
            pa[2] = Ps[(w16 + g    )*PSTR + kk + tig + 4];
            pa[3] = Ps[(w16 + g + 8)*PSTR + kk + tig + 4];
            #pragma unroll
            for (int nf = 0; nf < 12; nf++) {
                float bfr[2];
                bfr[0] = Vs[(kk + tig    )*VSTR + nf*8 + g];
                bfr[1] = Vs[(kk + tig + 4)*VSTR + nf*8 + g];
                mma_tf32(oa[nf], pa, bfr);
            }
        }
    }
    __syncthreads();

    // normalize + stage through smem [d][r] for coalesced store
    {
        float inv0 = 1.f / l_i[0], inv1 = 1.f / l_i[1];
        #pragma unroll
        for (int nf = 0; nf < 12; nf++) {
            int d = nf*8 + 2*tig;
            Qs[(d    )*BR + w16 + g    ] = oa[nf][0] * inv0;
            Qs[(d + 1)*BR + w16 + g    ] = oa[nf][1] * inv0;
            Qs[(d    )*BR + w16 + g + 8] = oa[nf][2] * inv1;
            Qs[(d + 1)*BR + w16 + g + 8] = oa[nf][3] * inv1;
        }
    }
    if (tig == 0) {
        Mo[((size_t)b*H_ + h)*T_ + t0 + w16 + g    ] = m_i[0];
        Lo[((size_t)b*H_ + h)*T_ + t0 + w16 + g    ] = l_i[0];
        Mo[((size_t)b*H_ + h)*T_ + t0 + w16 + g + 8] = m_i[1];
        Lo[((size_t)b*H_ + h)*T_ + t0 + w16 + g + 8] = l_i[1];
    }
    __syncthreads();
    float* Ob = O + base;
    for (int idx = tid; idx < D*BR; idx += 128) {
        int d = idx / BR, r = idx - d * BR;
        Ob[(size_t)d * T_ + t0 + r] = Qs[idx];
    }
}

// ---------------- relative-V band correction ----------------
__global__ __launch_bounds__(256) void k_relv(
    const float* __restrict__ Q, const float* __restrict__ Kp,
    const float* __restrict__ erk, const float* __restrict__ erv,
    const float* __restrict__ Mo, const float* __restrict__ Lo,
    float* __restrict__ O)
{
    __shared__ float Qt[96*32];
    __shared__ float Kt[96*40];
    __shared__ float ek[9*96], ev[9*96];

    const int t0 = blockIdx.x * 32;
    const int h = blockIdx.y, b = blockIdx.z;
    const size_t base = ((size_t)b * C_ + h * KC_) * T_;
    const int tid = threadIdx.x;

    for (int idx = tid; idx < 96*32; idx += 256) {
        int d = idx / 32, u = idx - d * 32;
        Qt[idx] = Q[base + (size_t)d * T_ + t0 + u] * SCALE_;
    }
    for (int idx = tid; idx < 96*40; idx += 256) {
        int d = idx / 40, u = idx - d * 40;
        int t = t0 - 4 + u;
        Kt[idx] = (t >= 0 && t < T_) ? Kp[base + (size_t)d * T_ + t] : 0.f;
    }
    for (int idx = tid; idx < 9*96; idx += 256) { ek[idx] = erk[idx]; ev[idx] = erv[idx]; }
    __syncthreads();

    const int tx = tid & 31, g = tid >> 5;
    const int t = t0 + tx;
    const float m = Mo[((size_t)b*H_ + h)*T_ + t];
    const float invl = 1.f / Lo[((size_t)b*H_ + h)*T_ + t];

    float p[9];
    #pragma unroll
    for (int dd = 0; dd < 9; dd++) {
        int s = t + dd - 4;
        if (s < 0 || s >= T_) { p[dd] = 0.f; continue; }
        float sc = 0.f;
        #pragma unroll 8
        for (int d = 0; d < 96; d++)
            sc = fmaf(Qt[d*32 + tx], Kt[d*40 + tx + dd] + ek[dd*96 + d], sc);
        p[dd] = __expf(sc - m) * invl;
    }
    #pragma unroll
    for (int jd = 0; jd < 12; jd++) {
        int d = g * 12 + jd;
        float add = 0.f;
        #pragma unroll
        for (int dd = 0; dd < 9; dd++) add = fmaf(p[dd], ev[dd*96 + d], add);
        O[base + (size_t)d * T_ + t] += add;
    }
}

// ---------------- fused residual-add + channel LayerNorm ----------------
__global__ __launch_bounds__(256) void k_addln(
    float* __restrict__ X, const float* __restrict__ R,
    const float* __restrict__ gg, const float* __restrict__ be)
{
    const int tx = threadIdx.x, ty = threadIdx.y;
    const int t = blockIdx.x * 32 + tx;
    const int b = blockIdx.y;

    float vals[24];
    float s = 0.f, sq = 0.f;
    #pragma unroll
    for (int k = 0; k < 24; k++) {
        int c = ty + k * 8;
        size_t idx = ((size_t)b * C_ + c) * T_ + t;
        float v = X[idx] + R[idx];
        vals[k] = v; s += v; sq += v * v;
    }
    __shared__ float ss[8][33], sg[8][33];
    ss[ty][tx] = s; sg[ty][tx] = sq;
    __syncthreads();
    if (ty == 0) {
        float a = 0.f, q = 0.f;
        #pragma unroll
        for (int k = 0; k < 8; k++) { a += ss[k][tx]; q += sg[k][tx]; }
        ss[0][tx] = a; sg[0][tx] = q;
    }
    __syncthreads();
    const float mean = ss[0][tx] * (1.f / C_);
    const float var  = sg[0][tx] * (1.f / C_) - mean * mean;
    const float rstd = rsqrtf(var + EPS_);
    #pragma unroll
    for (int k = 0; k < 24; k++) {
        int c = ty + k * 8;
        size_t idx = ((size_t)b * C_ + c) * T_ + t;
        X[idx] = (vals[k] - mean) * rstd * gg[c] + be[c];
    }
}

__global__ __launch_bounds__(256) void k_addln3(
    float* __restrict__ X, const float* __restrict__ R1, const float* __restrict__ R2,
    const float* __restrict__ gg, const float* __restrict__ be)
{
    const int tx = threadIdx.x, ty = threadIdx.y;
    const int t = blockIdx.x * 32 + tx;
    const int b = blockIdx.y;

    float vals[24];
    float s = 0.f, sq = 0.f;
    #pragma unroll
    for (int k = 0; k < 24; k++) {
        int c = ty + k * 8;
        size_t idx = ((size_t)b * C_ + c) * T_ + t;
        float v = X[idx] + R1[idx] + R2[idx];
        vals[k] = v; s += v; sq += v * v;
    }
    __shared__ float ss[8][33], sg[8][33];
    ss[ty][tx] = s; sg[ty][tx] = sq;
    __syncthreads();
    if (ty == 0) {
        float a = 0.f, q = 0.f;
        #pragma unroll
        for (int k = 0; k < 8; k++) { a += ss[k][tx]; q += sg[k][tx]; }
        ss[0][tx] = a; sg[0][tx] = q;
    }
    __syncthreads();
    const float mean = ss[0][tx] * (1.f / C_);
    const float var  = sg[0][tx] * (1.f / C_) - mean * mean;
    const float rstd = rsqrtf(var + EPS_);
    #pragma unroll
    for (int k = 0; k < 24; k++) {
        int c = ty + k * 8;
        size_t idx = ((size_t)b * C_ + c) * T_ + t;
        X[idx] = (vals[k] - mean) * rstd * gg[c] + be[c];
    }
}

// ---------------- launcher ----------------
extern "C" void kernel_launch(void* const* d_in, const int* in_sizes, int n_in,
                              void* d_out, int out_size)
{
    (void)in_sizes; (void)n_in; (void)out_size;
    const float* x   = (const float*)d_in[0];
    const float* msk = (const float*)d_in[1];
    const float* Wq  = (const float*)d_in[2];
    const float* bq  = (const float*)d_in[3];
    const float* Wk  = (const float*)d_in[4];
    const float* bk  = (const float*)d_in[5];
    const float* Wv  = (const float*)d_in[6];
    const float* bv  = (const float*)d_in[7];
    const float* Wo  = (const float*)d_in[8];
    const float* bo  = (const float*)d_in[9];
    const float* erk = (const float*)d_in[10];
    const float* erv = (const float*)d_in[11];
    const float* g1  = (const float*)d_in[12];
    const float* be1 = (const float*)d_in[13];
    const float* fw1 = (const float*)d_in[14];
    const float* fb1 = (const float*)d_in[15];
    const float* fw2 = (const float*)d_in[16];
    const float* fb2 = (const float*)d_in[17];
    const float* g2  = (const float*)d_in[18];
    const float* be2 = (const float*)d_in[19];

    float *xb, *qb, *kb, *vb, *ab, *tb, *fb, *mb, *lb;
    cudaGetSymbolAddress((void**)&xb, g_x);
    cudaGetSymbolAddress((void**)&qb, g_q);
    cudaGetSymbolAddress((void**)&kb, g_k);
    cudaGetSymbolAddress((void**)&vb, g_v);
    cudaGetSymbolAddress((void**)&ab, g_a);
    cudaGetSymbolAddress((void**)&tb, g_t);
    cudaGetSymbolAddress((void**)&fb, g_f);
    cudaGetSymbolAddress((void**)&mb, g_m);
    cudaGetSymbolAddress((void**)&lb, g_l);

    constexpr int FLASH_SMEM = (64*100 + 96*68 + 64*100 + 64*68 + 64*9) * 4;
    cudaFuncSetAttribute(k_flash, cudaFuncAttributeMaxDynamicSharedMemorySize, FLASH_SMEM);

    k_maskmul<<<(B_*C_*T_ + 255)/256, 256>>>(x, msk, xb);

    for (int i = 0; i < L_; i++) {
        k_qkv<<<dim3(T_/64, 9, B_), 256>>>(
            xb,
            Wq + (size_t)i*C_*C_, bq + i*C_, qb,
            Wk + (size_t)i*C_*C_, bk + i*C_, kb,
            Wv + (size_t)i*C_*C_, bv + i*C_, vb);

        k_flash<<<dim3(T_/64, H_, B_), 128, FLASH_SMEM>>>(
            qb, kb, vb, erk + (size_t)i*9*KC_, ab, mb, lb);
        k_relv<<<dim3(T_/32, H_, B_), 256>>>(
            qb, kb, erk + (size_t)i*9*KC_, erv + (size_t)i*9*KC_, mb, lb, ab);

        k_mma<1><<<dim3(T_/64, C_/64, B_), 256>>>(
            ab, Wo + (size_t)i*C_*C_, bo + i*C_, tb, C_, C_, 0);
        k_addln<<<dim3(T_/32, B_), dim3(32, 8)>>>(xb, tb, g1 + i*C_, be1 + i*C_);

        k_mma<3><<<dim3(T_/64, FC_/64, B_), 256>>>(
            xb, fw1 + (size_t)i*FC_*C_*3, fb1 + i*FC_, fb, FC_, C_, 1);

        k_conv2split<<<dim3(T_/64, 6, B_), 256>>>(
            fb, fw2 + (size_t)i*C_*FC_*3, fb2 + i*C_, tb, ab);
        k_addln3<<<dim3(T_/32, B_), dim3(32, 8)>>>(xb, tb, ab, g2 + i*C_, be2 + i*C_);
    }

    k_maskmul<<<(B_*C_*T_ + 255)/256, 256>>>(xb, msk, (float*)d_out);
}

// round 11
// speedup vs baseline: 2.8031x; 1.0458x over previous
#include <cuda_runtime.h>
#include <math.h>

// ---------------- problem constants ----------------
#define B_  4
#define C_  192
#define T_  2048
#define H_  2
#define KC_ 96
#define FC_ 768
#define L_  6
#define SCALE_ 0.10206207261596577f   // 96^-0.5
#define EPS_ 1e-5f

// ---------------- tf32 mma.sync helpers ----------------
__device__ __forceinline__ float to_tf32(float x) {
    unsigned r; asm("cvt.rna.tf32.f32 %0, %1;" : "=r"(r) : "f"(x));
    return __uint_as_float(r);
}
__device__ __forceinline__ void mma_tf32(float* d, const float* a, const float* b) {
    asm("mma.sync.aligned.m16n8k8.row.col.f32.tf32.tf32.f32 "
        "{%0,%1,%2,%3}, {%4,%5,%6,%7}, {%8,%9}, {%0,%1,%2,%3};"
        : "+f"(d[0]), "+f"(d[1]), "+f"(d[2]), "+f"(d[3])
        : "r"(__float_as_uint(a[0])), "r"(__float_as_uint(a[1])),
          "r"(__float_as_uint(a[2])), "r"(__float_as_uint(a[3])),
          "r"(__float_as_uint(b[0])), "r"(__float_as_uint(b[1])));
}

// ---------------- scratch (no allocations allowed) ----------------
__device__ float g_x[B_*C_*T_];
__device__ float g_q[B_*C_*T_];
__device__ float g_k[B_*C_*T_];
__device__ float g_v[B_*C_*T_];
__device__ float g_a[B_*C_*T_];
__device__ float g_t[B_*C_*T_];
__device__ float g_f[B_*FC_*T_];

// ---------------- elementwise mask multiply ----------------
__global__ void k_maskmul(const float* __restrict__ in, const float* __restrict__ msk,
                          float* __restrict__ out)
{
    int idx = blockIdx.x * blockDim.x + threadIdx.x;
    if (idx >= B_*C_*T_) return;
    int b = idx / (C_*T_);
    int t = idx % T_;
    out[idx] = in[idx] * msk[b*T_ + t];
}

// ---------------- tensor-core GEMM/conv body (tf32 mma.sync) ----------------
template<int KW>
__device__ __forceinline__ void mma_body(
    const float* __restrict__ Xb, const float* __restrict__ Wg,
    const float* __restrict__ bias, float* __restrict__ Yb,
    int Cin, int relu, int m0, int t0, int c_begin, int c_end)
{
    constexpr int BM = 64, BN = 64, BK = 32;
    constexpr int PADW = (KW - 1) / 2;
    constexpr int XV = BN + KW - 1;
    constexpr int ST = 72;               // 72 mod 32 == 8 -> conflict-free frags

    __shared__ float Ws[KW][BK][ST];
    __shared__ float Xs[BK][ST];

    const int tid  = threadIdx.x;
    const int lane = tid & 31, wid = tid >> 5;
    const int wm = wid >> 2, wn = wid & 3;
    const int g = lane >> 2, tig = lane & 3;
    const int mb = wm * 32, nb = wn * 16;

    float acc[2][2][4] = {};

    for (int c0 = c_begin; c0 < c_end; c0 += BK) {
        for (int idx = tid; idx < BM*BK*KW; idx += 256) {
            int o  = idx / (BK*KW);
            int ck = idx - o * (BK*KW);
            int c  = ck / KW, k = ck - c * KW;
            Ws[k][c][o] = to_tf32(Wg[((size_t)(m0 + o) * Cin + c0 + c) * KW + k]);
        }
        for (int idx = tid; idx < BK*XV; idx += 256) {
            int c = idx / XV, u = idx - c * XV;
            int t = t0 - PADW + u;
            Xs[c][u] = (t >= 0 && t < T_) ? to_tf32(Xb[(size_t)(c0 + c) * T_ + t]) : 0.f;
        }
        __syncthreads();

        #pragma unroll
        for (int kk = 0; kk < BK; kk += 8) {
            #pragma unroll
            for (int kw = 0; kw < KW; kw++) {
                float a[2][4], b[2][2];
                #pragma unroll
                for (int i = 0; i < 2; i++) {
                    a[i][0] = Ws[kw][kk + tig    ][mb + i*16 + g    ];
                    a[i][1] = Ws[kw][kk + tig    ][mb + i*16 + g + 8];
                    a[i][2] = Ws[kw][kk + tig + 4][mb + i*16 + g    ];
                    a[i][3] = Ws[kw][kk + tig + 4][mb + i*16 + g + 8];
                }
                #pragma unroll
                for (int j = 0; j < 2; j++) {
                    b[j][0] = Xs[kk + tig    ][nb + j*8 + g + kw];
                    b[j][1] = Xs[kk + tig + 4][nb + j*8 + g + kw];
                }
                #pragma unroll
                for (int i = 0; i < 2; i++)
                    #pragma unroll
                    for (int j = 0; j < 2; j++)
                        mma_tf32(acc[i][j], a[i], b[j]);
            }
        }
        __syncthreads();
    }

    #pragma unroll
    for (int i = 0; i < 2; i++) {
        int o0 = m0 + mb + i*16 + g;
        float b0 = bias ? bias[o0]     : 0.f;
        float b8 = bias ? bias[o0 + 8] : 0.f;
        #pragma unroll
        for (int j = 0; j < 2; j++) {
            int t = t0 + nb + j*8 + 2*tig;
            float2 v0 = make_float2(acc[i][j][0] + b0, acc[i][j][1] + b0);
            float2 v1 = make_float2(acc[i][j][2] + b8, acc[i][j][3] + b8);
            if (relu) {
                v0.x = fmaxf(v0.x, 0.f); v0.y = fmaxf(v0.y, 0.f);
                v1.x = fmaxf(v1.x, 0.f); v1.y = fmaxf(v1.y, 0.f);
            }
            *reinterpret_cast<float2*>(&Yb[(size_t)o0       * T_ + t]) = v0;
            *reinterpret_cast<float2*>(&Yb[(size_t)(o0 + 8) * T_ + t]) = v1;
        }
    }
}

template<int KW>
__global__ __launch_bounds__(256) void k_mma(
    const float* __restrict__ X, const float* __restrict__ Wg,
    const float* __restrict__ bias, float* __restrict__ Y,
    int M, int Cin, int relu)
{
    const int b = blockIdx.z;
    mma_body<KW>(X + (size_t)b * Cin * T_, Wg, bias, Y + (size_t)b * M * T_,
                 Cin, relu, blockIdx.y * 64, blockIdx.x * 64, 0, Cin);
}

__global__ __launch_bounds__(256) void k_qkv(
    const float* __restrict__ X,
    const float* __restrict__ Wq, const float* __restrict__ bq, float* __restrict__ Yq,
    const float* __restrict__ Wk, const float* __restrict__ bk, float* __restrict__ Yk,
    const float* __restrict__ Wv, const float* __restrict__ bv, float* __restrict__ Yv)
{
    const int b = blockIdx.z;
    const int mat = blockIdx.y / 3;
    const int m0  = (blockIdx.y % 3) * 64;
    const float *W, *bi; float *Y;
    if (mat == 0)      { W = Wq; bi = bq; Y = Yq; }
    else if (mat == 1) { W = Wk; bi = bk; Y = Yk; }
    else               { W = Wv; bi = bv; Y = Yv; }
    mma_body<1>(X + (size_t)b * C_ * T_, W, bi, Y + (size_t)b * C_ * T_,
                C_, 0, m0, blockIdx.x * 64, 0, C_);
}

__global__ __launch_bounds__(256) void k_conv2split(
    const float* __restrict__ X, const float* __restrict__ Wg,
    const float* __restrict__ bias, float* __restrict__ Y1, float* __restrict__ Y2)
{
    const int b = blockIdx.z;
    const int half = blockIdx.y / 3;
    const int m0   = (blockIdx.y % 3) * 64;
    float* Y = half ? Y2 : Y1;
    mma_body<3>(X + (size_t)b * FC_ * T_, Wg, half ? nullptr : bias,
                Y + (size_t)b * C_ * T_, FC_, 0, m0, blockIdx.x * 64,
                half * (FC_/2), (half + 1) * (FC_/2));
}

// ---------------- flash attention with fused rel-K band + rel-V correction ----
// 128 threads = 4 warps; warp w owns rows t0+16w .. t0+16w+15 end-to-end.
// Band scores (|s-t|<=4) are spilled to bs[][] during the diagonal tiles and
// converted to probabilities with the FINAL (m,l) in the epilogue, where the
// erv contribution is added directly to the normalized O. No separate pass.
__global__ __launch_bounds__(128) void k_flash(
    const float* __restrict__ Q, const float* __restrict__ Kp, const float* __restrict__ V,
    const float* __restrict__ erk, const float* __restrict__ erv,
    float* __restrict__ O)
{
    constexpr int BR = 64, BC = 64, D = 96;
    constexpr int QSTR = 100, KSTR = 68, VSTR = 100, PSTR = 68;
    extern __shared__ float sm[];
    float* Qs = sm;                  // BR*QSTR  [r][d] tf32(q*scale)
    float* Ks = Qs + BR*QSTR;        // D*KSTR   [d][s] tf32
    float* Vs = Ks + D*KSTR;         // BC*VSTR  [s][d] tf32
    float* Ps = Vs + BC*VSTR;        // BR*PSTR  [r][s] tf32 probabilities
    float* qr = Ps + BR*PSTR;        // BR*9     q . erk
    float* bs = qr + BR*9;           // BR*12    band scores (init -1e30)
    float* ev = bs + BR*12;          // 9*96     erv staged

    const int t0 = blockIdx.x * BR;
    const int h = blockIdx.y, b = blockIdx.z;
    const size_t base = ((size_t)b * C_ + h * KC_) * T_;
    const float* Qb = Q + base;
    const float* Kb = Kp + base;
    const float* Vb = V + base;

    const int tid  = threadIdx.x;
    const int lane = tid & 31, w = tid >> 5;
    const int g = lane >> 2, tig = lane & 3;
    const int w16 = w * 16;

    for (int idx = tid; idx < D*BR; idx += 128) {
        int d = idx / BR, r = idx - d * BR;
        Qs[r*QSTR + d] = to_tf32(Qb[(size_t)d * T_ + t0 + r] * SCALE_);
    }
    for (int idx = tid; idx < 9*96; idx += 128) ev[idx] = erv[idx];
    for (int idx = tid; idx < BR*12; idx += 128) bs[idx] = -1e30f;
    __syncthreads();
    for (int idx = tid; idx < BR * 9; idx += 128) {
        int r = idx / 9, dd = idx - r * 9;
        float s = 0.f;
        #pragma unroll 8
        for (int d = 0; d < D; d++) s = fmaf(Qs[r*QSTR + d], erk[dd*KC_ + d], s);
        qr[idx] = s;
    }

    float m_i[2] = {-1e30f, -1e30f};
    float l_i[2] = {0.f, 0.f};
    float oa[12][4] = {};

    for (int s0 = 0; s0 < T_; s0 += BC) {
        __syncthreads();
        for (int idx = tid; idx < D*BC; idx += 128) {
            int d = idx / BC, s = idx - d * BC;
            Ks[d*KSTR + s] = to_tf32(Kb[(size_t)d * T_ + s0 + s]);
            Vs[s*VSTR + d] = to_tf32(Vb[(size_t)d * T_ + s0 + s]);
        }
        __syncthreads();

        // ---- S = Q K^T ----
        float acc[8][4];
        #pragma unroll
        for (int nf = 0; nf < 8; nf++)
            #pragma unroll
            for (int e = 0; e < 4; e++) acc[nf][e] = 0.f;

        #pragma unroll
        for (int kk = 0; kk < D; kk += 8) {
            float a[4];
            a[0] = Qs[(w16 + g    )*QSTR + kk + tig    ];
            a[1] = Qs[(w16 + g + 8)*QSTR + kk + tig    ];
            a[2] = Qs[(w16 + g    )*QSTR + kk + tig + 4];
            a[3] = Qs[(w16 + g + 8)*QSTR + kk + tig + 4];
            #pragma unroll
            for (int nf = 0; nf < 8; nf++) {
                float bfr[2];
                bfr[0] = Ks[(kk + tig    )*KSTR + nf*8 + g];
                bfr[1] = Ks[(kk + tig + 4)*KSTR + nf*8 + g];
                mma_tf32(acc[nf], a, bfr);
            }
        }

        // ---- rel-K band add + band-score spill (diagonal tiles only) ----
        if (s0 + BC + 4 > t0 && s0 < t0 + BR + 5) {
            #pragma unroll
            for (int nf = 0; nf < 8; nf++)
                #pragma unroll
                for (int e = 0; e < 2; e++) {
                    int col = s0 + nf*8 + 2*tig + e;
                    int r0 = t0 + w16 + g;
                    int d0 = col - r0;
                    if (d0 >= -4 && d0 <= 4) {
                        acc[nf][e] += qr[(w16 + g)*9 + d0 + 4];
                        bs[(w16 + g)*12 + d0 + 4] = acc[nf][e];
                    }
                    int d1 = col - (r0 + 8);
                    if (d1 >= -4 && d1 <= 4) {
                        acc[nf][e + 2] += qr[(w16 + g + 8)*9 + d1 + 4];
                        bs[(w16 + g + 8)*12 + d1 + 4] = acc[nf][e + 2];
                    }
                }
        }

        // ---- online softmax (rows g and g+8; reduce over tig group) ----
        #pragma unroll
        for (int i = 0; i < 2; i++) {
            float mx = -1e30f;
            #pragma unroll
            for (int nf = 0; nf < 8; nf++)
                mx = fmaxf(mx, fmaxf(acc[nf][2*i], acc[nf][2*i + 1]));
            mx = fmaxf(mx, __shfl_xor_sync(0xffffffffu, mx, 1));
            mx = fmaxf(mx, __shfl_xor_sync(0xffffffffu, mx, 2));
            float mn = fmaxf(m_i[i], mx);
            float al = __expf(m_i[i] - mn);
            float rs = 0.f;
            int row = w16 + g + 8*i;
            #pragma unroll
            for (int nf = 0; nf < 8; nf++) {
                float p0 = to_tf32(__expf(acc[nf][2*i    ] - mn));
                float p1 = to_tf32(__expf(acc[nf][2*i + 1] - mn));
                *reinterpret_cast<float2*>(&Ps[row*PSTR + nf*8 + 2*tig]) = make_float2(p0, p1);
                rs += p0 + p1;
            }
            rs += __shfl_xor_sync(0xffffffffu, rs, 1);
            rs += __shfl_xor_sync(0xffffffffu, rs, 2);
            l_i[i] = l_i[i] * al + rs;
            m_i[i] = mn;
            #pragma unroll
            for (int nf = 0; nf < 12; nf++) {
                oa[nf][2*i] *= al; oa[nf][2*i + 1] *= al;
            }
        }
        __syncwarp();

        // ---- O += P @ V ----
        #pragma unroll
        for (int kk = 0; kk < BC; kk += 8) {
            float pa[4];
            pa[0] = Ps[(w16 + g    )*PSTR + kk + tig    ];
            pa[1] = Ps[(w16 + g + 8)*PSTR + kk + tig    ];
            pa[2] = Ps[(w16 + g    )*PSTR + kk + tig + 4];
            pa[3] = Ps[(w16 + g + 8)*PSTR + kk + tig + 4];
            #pragma unroll
            for (int nf = 0; nf < 12; nf++) {
                float bfr[2];
                bfr[0] = Vs[(kk + tig    )*VSTR + nf*8 + g];
                bfr[1] = Vs[(kk + tig + 4)*VSTR + nf*8 + g];
                mma_tf32(oa[nf], pa, bfr);
            }
        }
    }
    __syncthreads();   // also orders bs writes before epilogue reads

    // ---- epilogue: band probs from final (m,l); normalize + add erv term ----
    {
        float inv0 = 1.f / l_i[0], inv1 = 1.f / l_i[1];
        float p0[9], p1[9];
        #pragma unroll
        for (int dd = 0; dd < 9; dd++) {
            p0[dd] = __expf(bs[(w16 + g    )*12 + dd] - m_i[0]) * inv0;
            p1[dd] = __expf(bs[(w16 + g + 8)*12 + dd] - m_i[1]) * inv1;
        }
        #pragma unroll
        for (int nf = 0; nf < 12; nf++) {
            #pragma unroll
            for (int e = 0; e < 2; e++) {
                int d = nf*8 + 2*tig + e;
                float add0 = 0.f, add1 = 0.f;
                #pragma unroll
                for (int dd = 0; dd < 9; dd++) {
                    float evd = ev[dd*96 + d];
                    add0 = fmaf(p0[dd], evd, add0);
                    add1 = fmaf(p1[dd], evd, add1);
                }
                Qs[d*BR + w16 + g    ] = oa[nf][e    ] * inv0 + add0;
                Qs[d*BR + w16 + g + 8] = oa[nf][e + 2] * inv1 + add1;
            }
        }
    }
    __syncthreads();
    float* Ob = O + base;
    for (int idx = tid; idx < D*BR; idx += 128) {
        int d = idx / BR, r = idx - d * BR;
        Ob[(size_t)d * T_ + t0 + r] = Qs[idx];
    }
}

// ---------------- fused residual-add + channel LayerNorm ----------------
__global__ __launch_bounds__(256) void k_addln(
    float* __restrict__ X, const float* __restrict__ R,
    const float* __restrict__ gg, const float* __restrict__ be)
{
    const int tx = threadIdx.x, ty = threadIdx.y;
    const int t = blockIdx.x * 32 + tx;
    const int b = blockIdx.y;

    float vals[24];
    float s = 0.f, sq = 0.f;
    #pragma unroll
    for (int k = 0; k < 24; k++) {
        int c = ty + k * 8;
        size_t idx = ((size_t)b * C_ + c) * T_ + t;
        float v = X[idx] + R[idx];
        vals[k] = v; s += v; sq += v * v;
    }
    __shared__ float ss[8][33], sg[8][33];
    ss[ty][tx] = s; sg[ty][tx] = sq;
    __syncthreads();
    if (ty == 0) {
        float a = 0.f, q = 0.f;
        #pragma unroll
        for (int k = 0; k < 8; k++) { a += ss[k][tx]; q += sg[k][tx]; }
        ss[0][tx] = a; sg[0][tx] = q;
    }
    __syncthreads();
    const float mean = ss[0][tx] * (1.f / C_);
    const float var  = sg[0][tx] * (1.f / C_) - mean * mean;
    const float rstd = rsqrtf(var + EPS_);
    #pragma unroll
    for (int k = 0; k < 24; k++) {
        int c = ty + k * 8;
        size_t idx = ((size_t)b * C_ + c) * T_ + t;
        X[idx] = (vals[k] - mean) * rstd * gg[c] + be[c];
    }
}

__global__ __launch_bounds__(256) void k_addln3(
    float* __restrict__ X, const float* __restrict__ R1, const float* __restrict__ R2,
    const float* __restrict__ gg, const float* __restrict__ be)
{
    const int tx = threadIdx.x, ty = threadIdx.y;
    const int t = blockIdx.x * 32 + tx;
    const int b = blockIdx.y;

    float vals[24];
    float s = 0.f, sq = 0.f;
    #pragma unroll
    for (int k = 0; k < 24; k++) {
        int c = ty + k * 8;
        size_t idx = ((size_t)b * C_ + c) * T_ + t;
        float v = X[idx] + R1[idx] + R2[idx];
        vals[k] = v; s += v; sq += v * v;
    }
    __shared__ float ss[8][33], sg[8][33];
    ss[ty][tx] = s; sg[ty][tx] = sq;
    __syncthreads();
    if (ty == 0) {
        float a = 0.f, q = 0.f;
        #pragma unroll
        for (int k = 0; k < 8; k++) { a += ss[k][tx]; q += sg[k][tx]; }
        ss[0][tx] = a; sg[0][tx] = q;
    }
    __syncthreads();
    const float mean = ss[0][tx] * (1.f / C_);
    const float var  = sg[0][tx] * (1.f / C_) - mean * mean;
    const float rstd = rsqrtf(var + EPS_);
    #pragma unroll
    for (int k = 0; k < 24; k++) {
        int c = ty + k * 8;
        size_t idx = ((size_t)b * C_ + c) * T_ + t;
        X[idx] = (vals[k] - mean) * rstd * gg[c] + be[c];
    }
}

// ---------------- launcher ----------------
extern "C" void kernel_launch(void* const* d_in, const int* in_sizes, int n_in,
                              void* d_out, int out_size)
{
    (void)in_sizes; (void)n_in; (void)out_size;
    const float* x   = (const float*)d_in[0];
    const float* msk = (const float*)d_in[1];
    const float* Wq  = (const float*)d_in[2];
    const float* bq  = (const float*)d_in[3];
    const float* Wk  = (const float*)d_in[4];
    const float* bk  = (const float*)d_in[5];
    const float* Wv  = (const float*)d_in[6];
    const float* bv  = (const float*)d_in[7];
    const float* Wo  = (const float*)d_in[8];
    const float* bo  = (const float*)d_in[9];
    const float* erk = (const float*)d_in[10];
    const float* erv = (const float*)d_in[11];
    const float* g1  = (const float*)d_in[12];
    const float* be1 = (const float*)d_in[13];
    const float* fw1 = (const float*)d_in[14];
    const float* fb1 = (const float*)d_in[15];
    const float* fw2 = (const float*)d_in[16];
    const float* fb2 = (const float*)d_in[17];
    const float* g2  = (const float*)d_in[18];
    const float* be2 = (const float*)d_in[19];

    float *xb, *qb, *kb, *vb, *ab, *tb, *fb;
    cudaGetSymbolAddress((void**)&xb, g_x);
    cudaGetSymbolAddress((void**)&qb, g_q);
    cudaGetSymbolAddress((void**)&kb, g_k);
    cudaGetSymbolAddress((void**)&vb, g_v);
    cudaGetSymbolAddress((void**)&ab, g_a);
    cudaGetSymbolAddress((void**)&tb, g_t);
    cudaGetSymbolAddress((void**)&fb, g_f);

    constexpr int FLASH_SMEM =
        (64*100 + 96*68 + 64*100 + 64*68 + 64*9 + 64*12 + 9*96) * 4;
    cudaFuncSetAttribute(k_flash, cudaFuncAttributeMaxDynamicSharedMemorySize, FLASH_SMEM);

    k_maskmul<<<(B_*C_*T_ + 255)/256, 256>>>(x, msk, xb);

    for (int i = 0; i < L_; i++) {
        k_qkv<<<dim3(T_/64, 9, B_), 256>>>(
            xb,
            Wq + (size_t)i*C_*C_, bq + i*C_, qb,
            Wk + (size_t)i*C_*C_, bk + i*C_, kb,
            Wv + (size_t)i*C_*C_, bv + i*C_, vb);

        k_flash<<<dim3(T_/64, H_, B_), 128, FLASH_SMEM>>>(
            qb, kb, vb, erk + (size_t)i*9*KC_, erv + (size_t)i*9*KC_, ab);

        k_mma<1><<<dim3(T_/64, C_/64, B_), 256>>>(
            ab, Wo + (size_t)i*C_*C_, bo + i*C_, tb, C_, C_, 0);
        k_addln<<<dim3(T_/32, B_), dim3(32, 8)>>>(xb, tb, g1 + i*C_, be1 + i*C_);

        k_mma<3><<<dim3(T_/64, FC_/64, B_), 256>>>(
            xb, fw1 + (size_t)i*FC_*C_*3, fb1 + i*FC_, fb, FC_, C_, 1);

        k_conv2split<<<dim3(T_/64, 6, B_), 256>>>(
            fb, fw2 + (size_t)i*C_*FC_*3, fb2 + i*C_, tb, ab);
        k_addln3<<<dim3(T_/32, B_), dim3(32, 8)>>>(xb, tb, ab, g2 + i*C_, be2 + i*C_);
    }

    k_maskmul<<<(B_*C_*T_ + 255)/256, 256>>>(xb, msk, (float*)d_out);
}

// round 13
// speedup vs baseline: 2.9842x; 1.0646x over previous
#include <cuda_runtime.h>
#include <math.h>

// ---------------- problem constants ----------------
#define B_  4
#define C_  192
#define T_  2048
#define H_  2
#define KC_ 96
#define FC_ 768
#define L_  6
#define SCALE_ 0.10206207261596577f   // 96^-0.5
#define EPS_ 1e-5f

// ---------------- tf32 mma.sync helpers ----------------
__device__ __forceinline__ float to_tf32(float x) {
    unsigned r; asm("cvt.rna.tf32.f32 %0, %1;" : "=r"(r) : "f"(x));
    return __uint_as_float(r);
}
__device__ __forceinline__ void mma_tf32(float* d, const float* a, const float* b) {
    asm("mma.sync.aligned.m16n8k8.row.col.f32.tf32.tf32.f32 "
        "{%0,%1,%2,%3}, {%4,%5,%6,%7}, {%8,%9}, {%0,%1,%2,%3};"
        : "+f"(d[0]), "+f"(d[1]), "+f"(d[2]), "+f"(d[3])
        : "r"(__float_as_uint(a[0])), "r"(__float_as_uint(a[1])),
          "r"(__float_as_uint(a[2])), "r"(__float_as_uint(a[3])),
          "r"(__float_as_uint(b[0])), "r"(__float_as_uint(b[1])));
}

// ---------------- scratch (no allocations allowed) ----------------
__device__ float g_x[B_*C_*T_];
__device__ float g_q[B_*C_*T_];
__device__ float g_k[B_*C_*T_];
__device__ float g_v[B_*C_*T_];
__device__ float g_a[B_*C_*T_];
__device__ float g_t[B_*C_*T_];
__device__ float g_f[B_*FC_*T_];

// ---------------- elementwise mask multiply ----------------
__global__ void k_maskmul(const float* __restrict__ in, const float* __restrict__ msk,
                          float* __restrict__ out)
{
    int idx = blockIdx.x * blockDim.x + threadIdx.x;
    if (idx >= B_*C_*T_) return;
    int b = idx / (C_*T_);
    int t = idx % T_;
    out[idx] = in[idx] * msk[b*T_ + t];
}

// ---------------- tensor-core GEMM/conv body (tf32 mma.sync) ----------------
// Register-prefetch double buffering: next tile's gmem loads are issued before
// the current tile's MMA loop, so LDG latency overlaps with tensor-core work.
// tf32 RNA conversion happens at STS time -> math identical to prior rounds.
template<int KW>
__device__ __forceinline__ void mma_body(
    const float* __restrict__ Xb, const float* __restrict__ Wg,
    const float* __restrict__ bias, float* __restrict__ Yb,
    int Cin, int relu, int m0, int t0, int c_begin, int c_end)
{
    constexpr int BM = 64, BN = 64, BK = 32;
    constexpr int PADW = (KW - 1) / 2;
    constexpr int XV = BN + KW - 1;
    constexpr int ST = 72;               // 72 mod 32 == 8 -> conflict-free frags
    constexpr int NW = BM*BK*KW/256;     // W elems per thread (8 or 24)
    constexpr int NX = (BK*XV + 255)/256;// X elems per thread (8 or 9)

    __shared__ float Ws[KW][BK][ST];
    __shared__ float Xs[BK][ST];

    const int tid  = threadIdx.x;
    const int lane = tid & 31, wid = tid >> 5;
    const int wm = wid >> 2, wn = wid & 3;
    const int g = lane >> 2, tig = lane & 3;
    const int mb = wm * 32, nb = wn * 16;

    float acc[2][2][4] = {};
    float wr[NW], xr[NX];

    // ---- prologue: load first tile into registers ----
    {
        int c0 = c_begin;
        #pragma unroll
        for (int j = 0; j < NW; j++) {
            int idx = tid + j*256;
            int o  = idx / (BK*KW);
            int ck = idx - o * (BK*KW);
            int c  = ck / KW, k = ck - c * KW;
            wr[j] = Wg[((size_t)(m0 + o) * Cin + c0 + c) * KW + k];
        }
        #pragma unroll
        for (int j = 0; j < NX; j++) {
            int idx = tid + j*256;
            if (idx < BK*XV) {
                int c = idx / XV, u = idx - c * XV;
                int t = t0 - PADW + u;
                xr[j] = (t >= 0 && t < T_) ? Xb[(size_t)(c0 + c) * T_ + t] : 0.f;
            }
        }
    }

    for (int c0 = c_begin; c0 < c_end; c0 += BK) {
        __syncthreads();                 // prior compute done reading smem

        // ---- store prefetched tile to smem (with tf32 RNA cvt) ----
        #pragma unroll
        for (int j = 0; j < NW; j++) {
            int idx = tid + j*256;
            int o  = idx / (BK*KW);
            int ck = idx - o * (BK*KW);
            int c  = ck / KW, k = ck - c * KW;
            Ws[k][c][o] = to_tf32(wr[j]);
        }
        #pragma unroll
        for (int j = 0; j < NX; j++) {
            int idx = tid + j*256;
            if (idx < BK*XV) {
                int c = idx / XV, u = idx - c * XV;
                Xs[c][u] = to_tf32(xr[j]);
            }
        }
        __syncthreads();

        // ---- issue next tile's gmem loads (overlap with compute below) ----
        if (c0 + BK < c_end) {
            int cn = c0 + BK;
            #pragma unroll
            for (int j = 0; j < NW; j++) {
                int idx = tid + j*256;
                int o  = idx / (BK*KW);
                int ck = idx - o * (BK*KW);
                int c  = ck / KW, k = ck - c * KW;
                wr[j] = Wg[((size_t)(m0 + o) * Cin + cn + c) * KW + k];
            }
            #pragma unroll
            for (int j = 0; j < NX; j++) {
                int idx = tid + j*256;
                if (idx < BK*XV) {
                    int c = idx / XV, u = idx - c * XV;
                    int t = t0 - PADW + u;
                    xr[j] = (t >= 0 && t < T_) ? Xb[(size_t)(cn + c) * T_ + t] : 0.f;
                }
            }
        }

        // ---- compute ----
        #pragma unroll
        for (int kk = 0; kk < BK; kk += 8) {
            #pragma unroll
            for (int kw = 0; kw < KW; kw++) {
                float a[2][4], b[2][2];
                #pragma unroll
                for (int i = 0; i < 2; i++) {
                    a[i][0] = Ws[kw][kk + tig    ][mb + i*16 + g    ];
                    a[i][1] = Ws[kw][kk + tig    ][mb + i*16 + g + 8];
                    a[i][2] = Ws[kw][kk + tig + 4][mb + i*16 + g    ];
                    a[i][3] = Ws[kw][kk + tig + 4][mb + i*16 + g + 8];
                }
                #pragma unroll
                for (int j = 0; j < 2; j++) {
                    b[j][0] = Xs[kk + tig    ][nb + j*8 + g + kw];
                    b[j][1] = Xs[kk + tig + 4][nb + j*8 + g + kw];
                }
                #pragma unroll
                for (int i = 0; i < 2; i++)
                    #pragma unroll
                    for (int j = 0; j < 2; j++)
                        mma_tf32(acc[i][j], a[i], b[j]);
            }
        }
    }

    #pragma unroll
    for (int i = 0; i < 2; i++) {
        int o0 = m0 + mb + i*16 + g;
        float b0 = bias ? bias[o0]     : 0.f;
        float b8 = bias ? bias[o0 + 8] : 0.f;
        #pragma unroll
        for (int j = 0; j < 2; j++) {
            int t = t0 + nb + j*8 + 2*tig;
            float2 v0 = make_float2(acc[i][j][0] + b0, acc[i][j][1] + b0);
            float2 v1 = make_float2(acc[i][j][2] + b8, acc[i][j][3] + b8);
            if (relu) {
                v0.x = fmaxf(v0.x, 0.f); v0.y = fmaxf(v0.y, 0.f);
                v1.x = fmaxf(v1.x, 0.f); v1.y = fmaxf(v1.y, 0.f);
            }
            *reinterpret_cast<float2*>(&Yb[(size_t)o0       * T_ + t]) = v0;
            *reinterpret_cast<float2*>(&Yb[(size_t)(o0 + 8) * T_ + t]) = v1;
        }
    }
}

template<int KW>
__global__ __launch_bounds__(256) void k_mma(
    const float* __restrict__ X, const float* __restrict__ Wg,
    const float* __restrict__ bias, float* __restrict__ Y,
    int M, int Cin, int relu)
{
    const int b = blockIdx.z;
    mma_body<KW>(X + (size_t)b * Cin * T_, Wg, bias, Y + (size_t)b * M * T_,
                 Cin, relu, blockIdx.y * 64, blockIdx.x * 64, 0, Cin);
}

__global__ __launch_bounds__(256) void k_qkv(
    const float* __restrict__ X,
    const float* __restrict__ Wq, const float* __restrict__ bq, float* __restrict__ Yq,
    const float* __restrict__ Wk, const float* __restrict__ bk, float* __restrict__ Yk,
    const float* __restrict__ Wv, const float* __restrict__ bv, float* __restrict__ Yv)
{
    const int b = blockIdx.z;
    const int mat = blockIdx.y / 3;
    const int m0  = (blockIdx.y % 3) * 64;
    const float *W, *bi; float *Y;
    if (mat == 0)      { W = Wq; bi = bq; Y = Yq; }
    else if (mat == 1) { W = Wk; bi = bk; Y = Yk; }
    else               { W = Wv; bi = bv; Y = Yv; }
    mma_body<1>(X + (size_t)b * C_ * T_, W, bi, Y + (size_t)b * C_ * T_,
                C_, 0, m0, blockIdx.x * 64, 0, C_);
}

__global__ __launch_bounds__(256) void k_conv2split(
    const float* __restrict__ X, const float* __restrict__ Wg,
    const float* __restrict__ bias, float* __restrict__ Y1, float* __restrict__ Y2)
{
    const int b = blockIdx.z;
    const int half = blockIdx.y / 3;
    const int m0   = (blockIdx.y % 3) * 64;
    float* Y = half ? Y2 : Y1;
    mma_body<3>(X + (size_t)b * FC_ * T_, Wg, half ? nullptr : bias,
                Y + (size_t)b * C_ * T_, FC_, 0, m0, blockIdx.x * 64,
                half * (FC_/2), (half + 1) * (FC_/2));
}

// ---------------- flash attention with fused rel-K band + rel-V correction ----
__global__ __launch_bounds__(128) void k_flash(
    const float* __restrict__ Q, const float* __restrict__ Kp, const float* __restrict__ V,
    const float* __restrict__ erk, const float* __restrict__ erv,
    float* __restrict__ O)
{
    constexpr int BR = 64, BC = 64, D = 96;
    constexpr int QSTR = 100, KSTR = 68, VSTR = 100, PSTR = 68;
    extern __shared__ float sm[];
    float* Qs = sm;                  // BR*QSTR  [r][d] tf32(q*scale)
    float* Ks = Qs + BR*QSTR;        // D*KSTR   [d][s] tf32
    float* Vs = Ks + D*KSTR;         // BC*VSTR  [s][d] tf32
    float* Ps = Vs + BC*VSTR;        // BR*PSTR  [r][s] tf32 probabilities
    float* qr = Ps + BR*PSTR;        // BR*9     q . erk
    float* bs = qr + BR*9;           // BR*12    band scores (init -1e30)
    float* ev = bs + BR*12;          // 9*96     erv staged

    const int t0 = blockIdx.x * BR;
    const int h = blockIdx.y, b = blockIdx.z;
    const size_t base = ((size_t)b * C_ + h * KC_) * T_;
    const float* Qb = Q + base;
    const float* Kb = Kp + base;
    const float* Vb = V + base;

    const int tid  = threadIdx.x;
    const int lane = tid & 31, w = tid >> 5;
    const int g = lane >> 2, tig = lane & 3;
    const int w16 = w * 16;

    for (int idx = tid; idx < D*BR; idx += 128) {
        int d = idx / BR, r = idx - d * BR;
        Qs[r*QSTR + d] = to_tf32(Qb[(size_t)d * T_ + t0 + r] * SCALE_);
    }
    for (int idx = tid; idx < 9*96; idx += 128) ev[idx] = erv[idx];
    for (int idx = tid; idx < BR*12; idx += 128) bs[idx] = -1e30f;
    __syncthreads();
    for (int idx = tid; idx < BR * 9; idx += 128) {
        int r = idx / 9, dd = idx - r * 9;
        float s = 0.f;
        #pragma unroll 8
        for (int d = 0; d < D; d++) s = fmaf(Qs[r*QSTR + d], erk[dd*KC_ + d], s);
        qr[idx] = s;
    }

    float m_i[2] = {-1e30f, -1e30f};
    float l_i[2] = {0.f, 0.f};
    float oa[12][4] = {};

    for (int s0 = 0; s0 < T_; s0 += BC) {
        __syncthreads();
        for (int idx = tid; idx < D*BC; idx += 128) {
            int d = idx / BC, s = idx - d * BC;
            Ks[d*KSTR + s] = to_tf32(Kb[(size_t)d * T_ + s0 + s]);
            Vs[s*VSTR + d] = to_tf32(Vb[(size_t)d * T_ + s0 + s]);
        }
        __syncthreads();

        // ---- S = Q K^T ----
        float acc[8][4];
        #pragma unroll
        for (int nf = 0; nf < 8; nf++)
            #pragma unroll
            for (int e = 0; e < 4; e++) acc[nf][e] = 0.f;

        #pragma unroll
        for (int kk = 0; kk < D; kk += 8) {
            float a[4];
            a[0] = Qs[(w16 + g    )*QSTR + kk + tig    ];
            a[1] = Qs[(w16 + g + 8)*QSTR + kk + tig    ];
            a[2] = Qs[(w16 + g    )*QSTR + kk + tig + 4];
            a[3] = Qs[(w16 + g + 8)*QSTR + kk + tig + 4];
            #pragma unroll
            for (int nf = 0; nf < 8; nf++) {
                float bfr[2];
                bfr[0] = Ks[(kk + tig    )*KSTR + nf*8 + g];
                bfr[1] = Ks[(kk + tig + 4)*KSTR + nf*8 + g];
                mma_tf32(acc[nf], a, bfr);
            }
        }

        // ---- rel-K band add + band-score spill (diagonal tiles only) ----
        if (s0 + BC + 4 > t0 && s0 < t0 + BR + 5) {
            #pragma unroll
            for (int nf = 0; nf < 8; nf++)
                #pragma unroll
                for (int e = 0; e < 2; e++) {
                    int col = s0 + nf*8 + 2*tig + e;
                    int r0 = t0 + w16 + g;
                    int d0 = col - r0;
                    if (d0 >= -4 && d0 <= 4) {
                        acc[nf][e] += qr[(w16 + g)*9 + d0 + 4];
                        bs[(w16 + g)*12 + d0 + 4] = acc[nf][e];
                    }
                    int d1 = col - (r0 + 8);
                    if (d1 >= -4 && d1 <= 4) {
                        acc[nf][e + 2] += qr[(w16 + g + 8)*9 + d1 + 4];
                        bs[(w16 + g + 8)*12 + d1 + 4] = acc[nf][e + 2];
                    }
                }
        }

        // ---- online softmax (rows g and g+8; reduce over tig group) ----
        #pragma unroll
        for (int i = 0; i < 2; i++) {
            float mx = -1e30f;
            #pragma unroll
            for (int nf = 0; nf < 8; nf++)
                mx = fmaxf(mx, fmaxf(acc[nf][2*i], acc[nf][2*i + 1]));
            mx = fmaxf(mx, __shfl_xor_sync(0xffffffffu, mx, 1));
            mx = fmaxf(mx, __shfl_xor_sync(0xffffffffu, mx, 2));
            float mn = fmaxf(m_i[i], mx);
            float al = __expf(m_i[i] - mn);
            float rs = 0.f;
            int row = w16 + g + 8*i;
            #pragma unroll
            for (int nf = 0; nf < 8; nf++) {
                float p0 = to_tf32(__expf(acc[nf][2*i    ] - mn));
                float p1 = to_tf32(__expf(acc[nf][2*i + 1] - mn));
                *reinterpret_cast<float2*>(&Ps[row*PSTR + nf*8 + 2*tig]) = make_float2(p0, p1);
                rs += p0 + p1;
            }
            rs += __shfl_xor_sync(0xffffffffu, rs, 1);
            rs += __shfl_xor_sync(0xffffffffu, rs, 2);
            l_i[i] = l_i[i] * al + rs;
            m_i[i] = mn;
            #pragma unroll
            for (int nf = 0; nf < 12; nf++) {
                oa[nf][2*i] *= al; oa[nf][2*i + 1] *= al;
            }
        }
        __syncwarp();

        // ---- O += P @ V ----
        #pragma unroll
        for (int kk = 0; kk < BC; kk += 8) {
            float pa[4];
            pa[0] = Ps[(w16 + g    )*PSTR + kk + tig    ];
            pa[1] = Ps[(w16 + g + 8)*PSTR + kk + tig    ];
            pa[2] = Ps[(w16 + g    )*PSTR + kk + tig + 4];
            pa[3] = Ps[(w16 + g + 8)*PSTR + kk + tig + 4];
            #pragma unroll
            for (int nf = 0; nf < 12; nf++) {
                float bfr[2];
                bfr[0] = Vs[(kk + tig    )*VSTR + nf*8 + g];
                bfr[1] = Vs[(kk + tig + 4)*VSTR + nf*8 + g];
                mma_tf32(oa[nf], pa, bfr);
            }
        }
    }
    __syncthreads();   // also orders bs writes before epilogue reads

    // ---- epilogue: band probs from final (m,l); normalize + add erv term ----
    {
        float inv0 = 1.f / l_i[0], inv1 = 1.f / l_i[1];
        float p0[9], p1[9];
        #pragma unroll
        for (int dd = 0; dd < 9; dd++) {
            p0[dd] = __expf(bs[(w16 + g    )*12 + dd] - m_i[0]) * inv0;
            p1[dd] = __expf(bs[(w16 + g + 8)*12 + dd] - m_i[1]) * inv1;
        }
        #pragma unroll
        for (int nf = 0; nf < 12; nf++) {
            #pragma unroll
            for (int e = 0; e < 2; e++) {
                int d = nf*8 + 2*tig + e;
                float add0 = 0.f, add1 = 0.f;
                #pragma unroll
                for (int dd = 0; dd < 9; dd++) {
                    float evd = ev[dd*96 + d];
                    add0 = fmaf(p0[dd], evd, add0);
                    add1 = fmaf(p1[dd], evd, add1);
                }
                Qs[d*BR + w16 + g    ] = oa[nf][e    ] * inv0 + add0;
                Qs[d*BR + w16 + g + 8] = oa[nf][e + 2] * inv1 + add1;
            }
        }
    }
    __syncthreads();
    float* Ob = O + base;
    for (int idx = tid; idx < D*BR; idx += 128) {
        int d = idx / BR, r = idx - d * BR;
        Ob[(size_t)d * T_ + t0 + r] = Qs[idx];
    }
}

// ---------------- fused residual-add + channel LayerNorm ----------------
__global__ __launch_bounds__(256) void k_addln(
    float* __restrict__ X, const float* __restrict__ R,
    const float* __restrict__ gg, const float* __restrict__ be)
{
    const int tx = threadIdx.x, ty = threadIdx.y;
    const int t = blockIdx.x * 32 + tx;
    const int b = blockIdx.y;

    float vals[24];
    float s = 0.f, sq = 0.f;
    #pragma unroll
    for (int k = 0; k < 24; k++) {
        int c = ty + k * 8;
        size_t idx = ((size_t)b * C_ + c) * T_ + t;
        float v = X[idx] + R[idx];
        vals[k] = v; s += v; sq += v * v;
    }
    __shared__ float ss[8][33], sg[8][33];
    ss[ty][tx] = s; sg[ty][tx] = sq;
    __syncthreads();
    if (ty == 0) {
        float a = 0.f, q = 0.f;
        #pragma unroll
        for (int k = 0; k < 8; k++) { a += ss[k][tx]; q += sg[k][tx]; }
        ss[0][tx] = a; sg[0][tx] = q;
    }
    __syncthreads();
    const float mean = ss[0][tx] * (1.f / C_);
    const float var  = sg[0][tx] * (1.f / C_) - mean * mean;
    const float rstd = rsqrtf(var + EPS_);
    #pragma unroll
    for (int k = 0; k < 24; k++) {
        int c = ty + k * 8;
        size_t idx = ((size_t)b * C_ + c) * T_ + t;
        X[idx] = (vals[k] - mean) * rstd * gg[c] + be[c];
    }
}

__global__ __launch_bounds__(256) void k_addln3(
    float* __restrict__ X, const float* __restrict__ R1, const float* __restrict__ R2,
    const float* __restrict__ gg, const float* __restrict__ be)
{
    const int tx = threadIdx.x, ty = threadIdx.y;
    const int t = blockIdx.x * 32 + tx;
    const int b = blockIdx.y;

    float vals[24];
    float s = 0.f, sq = 0.f;
    #pragma unroll
    for (int k = 0; k < 24; k++) {
        int c = ty + k * 8;
        size_t idx = ((size_t)b * C_ + c) * T_ + t;
        float v = X[idx] + R1[idx] + R2[idx];
        vals[k] = v; s += v; sq += v * v;
    }
    __shared__ float ss[8][33], sg[8][33];
    ss[ty][tx] = s; sg[ty][tx] = sq;
    __syncthreads();
    if (ty == 0) {
        float a = 0.f, q = 0.f;
        #pragma unroll
        for (int k = 0; k < 8; k++) { a += ss[k][tx]; q += sg[k][tx]; }
        ss[0][tx] = a; sg[0][tx] = q;
    }
    __syncthreads();
    const float mean = ss[0][tx] * (1.f / C_);
    const float var  = sg[0][tx] * (1.f / C_) - mean * mean;
    const float rstd = rsqrtf(var + EPS_);
    #pragma unroll
    for (int k = 0; k < 24; k++) {
        int c = ty + k * 8;
        size_t idx = ((size_t)b * C_ + c) * T_ + t;
        X[idx] = (vals[k] - mean) * rstd * gg[c] + be[c];
    }
}

// ---------------- launcher ----------------
extern "C" void kernel_launch(void* const* d_in, const int* in_sizes, int n_in,
                              void* d_out, int out_size)
{
    (void)in_sizes; (void)n_in; (void)out_size;
    const float* x   = (const float*)d_in[0];
    const float* msk = (const float*)d_in[1];
    const float* Wq  = (const float*)d_in[2];
    const float* bq  = (const float*)d_in[3];
    const float* Wk  = (const float*)d_in[4];
    const float* bk  = (const float*)d_in[5];
    const float* Wv  = (const float*)d_in[6];
    const float* bv  = (const float*)d_in[7];
    const float* Wo  = (const float*)d_in[8];
    const float* bo  = (const float*)d_in[9];
    const float* erk = (const float*)d_in[10];
    const float* erv = (const float*)d_in[11];
    const float* g1  = (const float*)d_in[12];
    const float* be1 = (const float*)d_in[13];
    const float* fw1 = (const float*)d_in[14];
    const float* fb1 = (const float*)d_in[15];
    const float* fw2 = (const float*)d_in[16];
    const float* fb2 = (const float*)d_in[17];
    const float* g2  = (const float*)d_in[18];
    const float* be2 = (const float*)d_in[19];

    float *xb, *qb, *kb, *vb, *ab, *tb, *fb;
    cudaGetSymbolAddress((void**)&xb, g_x);
    cudaGetSymbolAddress((void**)&qb, g_q);
    cudaGetSymbolAddress((void**)&kb, g_k);
    cudaGetSymbolAddress((void**)&vb, g_v);
    cudaGetSymbolAddress((void**)&ab, g_a);
    cudaGetSymbolAddress((void**)&tb, g_t);
    cudaGetSymbolAddress((void**)&fb, g_f);

    constexpr int FLASH_SMEM =
        (64*100 + 96*68 + 64*100 + 64*68 + 64*9 + 64*12 + 9*96) * 4;
    cudaFuncSetAttribute(k_flash, cudaFuncAttributeMaxDynamicSharedMemorySize, FLASH_SMEM);

    k_maskmul<<<(B_*C_*T_ + 255)/256, 256>>>(x, msk, xb);

    for (int i = 0; i < L_; i++) {
        k_qkv<<<dim3(T_/64, 9, B_), 256>>>(
            xb,
            Wq + (size_t)i*C_*C_, bq + i*C_, qb,
            Wk + (size_t)i*C_*C_, bk + i*C_, kb,
            Wv + (size_t)i*C_*C_, bv + i*C_, vb);

        k_flash<<<dim3(T_/64, H_, B_), 128, FLASH_SMEM>>>(
            qb, kb, vb, erk + (size_t)i*9*KC_, erv + (size_t)i*9*KC_, ab);

        k_mma<1><<<dim3(T_/64, C_/64, B_), 256>>>(
            ab, Wo + (size_t)i*C_*C_, bo + i*C_, tb, C_, C_, 0);
        k_addln<<<dim3(T_/32, B_), dim3(32, 8)>>>(xb, tb, g1 + i*C_, be1 + i*C_);

        k_mma<3><<<dim3(T_/64, FC_/64, B_), 256>>>(
            xb, fw1 + (size_t)i*FC_*C_*3, fb1 + i*FC_, fb, FC_, C_, 1);

        k_conv2split<<<dim3(T_/64, 6, B_), 256>>>(
            fb, fw2 + (size_t)i*C_*FC_*3, fb2 + i*C_, tb, ab);
        k_addln3<<<dim3(T_/32, B_), dim3(32, 8)>>>(xb, tb, ab, g2 + i*C_, be2 + i*C_);
    }

    k_maskmul<<<(B_*C_*T_ + 255)/256, 256>>>(xb, msk, (float*)d_out);
}